// round 2
// baseline (speedup 1.0000x reference)
#include <cuda_runtime.h>
#include <math.h>

#define NRES 8192
#define NK   48
#define NH   128

// Scratch (device globals: no allocation allowed in kernel_launch)
__device__ float g_Pi[NRES * NH];   // node_h @ W1a
__device__ float g_Pj[NRES * NH];   // node_h @ W1b
__device__ float g_Ps[NRES * NH];   // seq_emb @ W1d
__device__ float g_agg[NRES * NH];  // sum_k msg

__device__ __forceinline__ float gelu_exact(float x) {
    return 0.5f * x * (1.0f + erff(x * 0.7071067811865475f));
}

// ---------------------------------------------------------------------------
// Kernel 1: precompute the three per-residue projections of mW1.
//   which==0: g_Pi = node_h @ mW1[0:128]
//   which==1: g_Pj = node_h @ mW1[128:256]
//   which==2: g_Ps = seq_emb @ mW1[384:512]
// Tile M=64, N=128, K=128. 256 threads, 4x8 accumulators/thread.
// ---------------------------------------------------------------------------
__global__ __launch_bounds__(256) void k1_pre(const float* __restrict__ node_h,
                                              const float* __restrict__ seq_emb,
                                              const float* __restrict__ mW1) {
    extern __shared__ float sm1[];
    float* Wsh = sm1;            // 128*128
    float* Ash = sm1 + 16384;    // 64*132 (padded rows)

    const int tid   = threadIdx.x;
    const int which = blockIdx.y;
    const float* A    = (which == 2) ? seq_emb : node_h;
    const float* Wsrc = mW1 + (size_t)(which == 0 ? 0 : (which == 1 ? 128 : 384)) * NH;
    float* out = (which == 0) ? g_Pi : (which == 1 ? g_Pj : g_Ps);

    for (int i = tid; i < 4096; i += 256)
        ((float4*)Wsh)[i] = ((const float4*)Wsrc)[i];

    const int m0 = blockIdx.x * 64;
    for (int i = tid; i < 64 * 32; i += 256) {
        int r = i >> 5, c4 = i & 31;
        *(float4*)&Ash[r * 132 + c4 * 4] = ((const float4*)(A + (size_t)(m0 + r) * NH))[c4];
    }
    __syncthreads();

    const int tc = tid & 15, tr = tid >> 4;
    float acc[4][8];
#pragma unroll
    for (int i = 0; i < 4; i++)
#pragma unroll
        for (int j = 0; j < 8; j++) acc[i][j] = 0.f;

#pragma unroll 4
    for (int kk = 0; kk < 128; kk++) {
        float4 b0 = *(const float4*)&Wsh[kk * 128 + tc * 8];
        float4 b1 = *(const float4*)&Wsh[kk * 128 + tc * 8 + 4];
#pragma unroll
        for (int i = 0; i < 4; i++) {
            float a = Ash[(tr * 4 + i) * 132 + kk];
            acc[i][0] = fmaf(a, b0.x, acc[i][0]);
            acc[i][1] = fmaf(a, b0.y, acc[i][1]);
            acc[i][2] = fmaf(a, b0.z, acc[i][2]);
            acc[i][3] = fmaf(a, b0.w, acc[i][3]);
            acc[i][4] = fmaf(a, b1.x, acc[i][4]);
            acc[i][5] = fmaf(a, b1.y, acc[i][5]);
            acc[i][6] = fmaf(a, b1.z, acc[i][6]);
            acc[i][7] = fmaf(a, b1.w, acc[i][7]);
        }
    }
#pragma unroll
    for (int i = 0; i < 4; i++) {
        size_t r = (size_t)(m0 + tr * 4 + i) * NH + tc * 8;
#pragma unroll
        for (int j = 0; j < 8; j++) out[r + j] = acc[i][j];
    }
}

// ---------------------------------------------------------------------------
// Kernel 2: per-edge message MLP, fused + aggregated.
// Persistent: each CTA processes residue PAIRS (96 edge rows) in a stride loop.
// Per pair:
//   X1 = gelu(E @ W1c + Pi[res] + Pj[nbr] + am*Ps[nbr] + mb1)   [96 x 128]
//   X2 = gelu(X1 @ W2 + mb2)                                    [96 x 128]
//   s[res] = sum over 48 rows of X2
//   agg[res] = s @ W3 + 48*mb3        (GEMV: sum-before-GEMM3 identity)
// Weights W1c/W2 resident in SMEM; activations in SMEM; accumulators in regs.
// ---------------------------------------------------------------------------
__global__ __launch_bounds__(256) void k2_msg(const float* __restrict__ edge_h,
                                              const int*   __restrict__ edge_idx,
                                              const float* __restrict__ ar_mask,
                                              const float* __restrict__ mW1,
                                              const float* __restrict__ mb1,
                                              const float* __restrict__ mW2,
                                              const float* __restrict__ mb2,
                                              const float* __restrict__ mW3,
                                              const float* __restrict__ mb3,
                                              int npairs) {
    extern __shared__ float sm2[];
    float* W1sh = sm2;              // 128*128   (W1c = mW1 rows 256..383)
    float* W2sh = sm2 + 16384;      // 128*128
    float* Bsh  = sm2 + 32768;      // 96*132 activation buffer (padded)
    float* Ssh  = sm2 + 32768 + 96 * 132;  // 2*128 column sums
    __shared__ int   idx_sh[96];
    __shared__ float am_sh[96];

    const int tid = threadIdx.x;
    for (int i = tid; i < 4096; i += 256) {
        ((float4*)W1sh)[i] = ((const float4*)(mW1 + 256 * NH))[i];
        ((float4*)W2sh)[i] = ((const float4*)mW2)[i];
    }

    const int tc = tid & 15, tr = tid >> 4;

    for (int p = blockIdx.x; p < npairs; p += gridDim.x) {
        __syncthreads();  // separate from previous iteration's reads
        const int r0 = p * 2;
        if (tid < 96) {
            idx_sh[tid] = edge_idx[(size_t)r0 * NK + tid];
            am_sh[tid]  = ar_mask[(size_t)r0 * NK + tid];
        }
        // load edge tile: 96 rows x 128 cols (contiguous for the 2 residues)
        const float4* Esrc = (const float4*)(edge_h + (size_t)r0 * NK * NH);
        for (int i = tid; i < 96 * 32; i += 256) {
            int r = i >> 5, c4 = i & 31;
            *(float4*)&Bsh[r * 132 + c4 * 4] = Esrc[i];
        }
        __syncthreads();

        // ---- GEMM1: acc = base + E @ W1c ----
        float acc[6][8];
#pragma unroll
        for (int i = 0; i < 6; i++) {
            int r   = tr * 6 + i;
            int res = r0 + (r >= 48 ? 1 : 0);
            int nbr = idx_sh[r];
            float amv = am_sh[r];
            const float4* pi = (const float4*)(g_Pi + (size_t)res * NH + tc * 8);
            const float4* pj = (const float4*)(g_Pj + (size_t)nbr * NH + tc * 8);
            const float4* ps = (const float4*)(g_Ps + (size_t)nbr * NH + tc * 8);
            const float4* bb = (const float4*)(mb1 + tc * 8);
#pragma unroll
            for (int h = 0; h < 2; h++) {
                float4 A = pi[h], B = pj[h], C = ps[h], D = bb[h];
                acc[i][h * 4 + 0] = A.x + B.x + amv * C.x + D.x;
                acc[i][h * 4 + 1] = A.y + B.y + amv * C.y + D.y;
                acc[i][h * 4 + 2] = A.z + B.z + amv * C.z + D.z;
                acc[i][h * 4 + 3] = A.w + B.w + amv * C.w + D.w;
            }
        }
#pragma unroll 4
        for (int kk = 0; kk < 128; kk++) {
            float4 b0 = *(const float4*)&W1sh[kk * 128 + tc * 8];
            float4 b1 = *(const float4*)&W1sh[kk * 128 + tc * 8 + 4];
#pragma unroll
            for (int i = 0; i < 6; i++) {
                float a = Bsh[(tr * 6 + i) * 132 + kk];
                acc[i][0] = fmaf(a, b0.x, acc[i][0]);
                acc[i][1] = fmaf(a, b0.y, acc[i][1]);
                acc[i][2] = fmaf(a, b0.z, acc[i][2]);
                acc[i][3] = fmaf(a, b0.w, acc[i][3]);
                acc[i][4] = fmaf(a, b1.x, acc[i][4]);
                acc[i][5] = fmaf(a, b1.y, acc[i][5]);
                acc[i][6] = fmaf(a, b1.z, acc[i][6]);
                acc[i][7] = fmaf(a, b1.w, acc[i][7]);
            }
        }
        // gelu, write X1 back
#pragma unroll
        for (int i = 0; i < 6; i++)
#pragma unroll
            for (int j = 0; j < 8; j++) acc[i][j] = gelu_exact(acc[i][j]);
        __syncthreads();
#pragma unroll
        for (int i = 0; i < 6; i++)
#pragma unroll
            for (int j = 0; j < 8; j++) Bsh[(tr * 6 + i) * 132 + tc * 8 + j] = acc[i][j];
        __syncthreads();

        // ---- GEMM2: acc = mb2 + X1 @ W2 ----
#pragma unroll
        for (int i = 0; i < 6; i++)
#pragma unroll
            for (int j = 0; j < 8; j++) acc[i][j] = mb2[tc * 8 + j];
#pragma unroll 4
        for (int kk = 0; kk < 128; kk++) {
            float4 b0 = *(const float4*)&W2sh[kk * 128 + tc * 8];
            float4 b1 = *(const float4*)&W2sh[kk * 128 + tc * 8 + 4];
#pragma unroll
            for (int i = 0; i < 6; i++) {
                float a = Bsh[(tr * 6 + i) * 132 + kk];
                acc[i][0] = fmaf(a, b0.x, acc[i][0]);
                acc[i][1] = fmaf(a, b0.y, acc[i][1]);
                acc[i][2] = fmaf(a, b0.z, acc[i][2]);
                acc[i][3] = fmaf(a, b0.w, acc[i][3]);
                acc[i][4] = fmaf(a, b1.x, acc[i][4]);
                acc[i][5] = fmaf(a, b1.y, acc[i][5]);
                acc[i][6] = fmaf(a, b1.z, acc[i][6]);
                acc[i][7] = fmaf(a, b1.w, acc[i][7]);
            }
        }
#pragma unroll
        for (int i = 0; i < 6; i++)
#pragma unroll
            for (int j = 0; j < 8; j++) acc[i][j] = gelu_exact(acc[i][j]);
        __syncthreads();
#pragma unroll
        for (int i = 0; i < 6; i++)
#pragma unroll
            for (int j = 0; j < 8; j++) Bsh[(tr * 6 + i) * 132 + tc * 8 + j] = acc[i][j];
        __syncthreads();

        // ---- column sums over K=48 rows per residue ----
        {
            int res_l = tid >> 7;      // 0..1
            int col   = tid & 127;
            float s = 0.f;
#pragma unroll 8
            for (int k = 0; k < 48; k++) s += Bsh[(res_l * 48 + k) * 132 + col];
            Ssh[res_l * 128 + col] = s;
        }
        __syncthreads();

        // ---- GEMV: agg = s @ W3 + 48*mb3 ----
        {
            int res_l = tid >> 7;
            int col   = tid & 127;
            const float* srow = &Ssh[res_l * 128];
            float v = 48.f * mb3[col];
#pragma unroll 8
            for (int k = 0; k < 128; k++) v = fmaf(srow[k], mW3[k * 128 + col], v);
            g_agg[(size_t)(r0 + res_l) * NH + col] = v;
        }
    }
}

// ---------------------------------------------------------------------------
// Kernel 3: h = LN1(node_h + agg); out = LN2(h + FFN(h))
// 32 residues per CTA, FFN weights streamed in 128-col/row chunks.
// ---------------------------------------------------------------------------
__global__ __launch_bounds__(256) void k3_ff(const float* __restrict__ node_h,
                                             const float* __restrict__ fW1,
                                             const float* __restrict__ fb1,
                                             const float* __restrict__ fW2,
                                             const float* __restrict__ fb2,
                                             const float* __restrict__ g1,
                                             const float* __restrict__ b1,
                                             const float* __restrict__ g2,
                                             const float* __restrict__ b2,
                                             float* __restrict__ out) {
    extern __shared__ float sm3[];
    float* H1sh = sm3;                 // 32*132
    float* Tsh  = sm3 + 32 * 132;      // 32*516
    float* Wsh  = sm3 + 32 * 132 + 32 * 516;  // 128*128

    const int tid  = threadIdx.x;
    const int wid  = tid >> 5, lane = tid & 31;
    const int m0   = blockIdx.x * 32;

    // step 1: u = node_h + agg; LN1 -> H1sh
    for (int r = wid; r < 32; r += 8) {
        const int c0 = lane * 4;
        float4 a = *(const float4*)&node_h[(size_t)(m0 + r) * NH + c0];
        float4 g = *(const float4*)&g_agg[(size_t)(m0 + r) * NH + c0];
        float v0 = a.x + g.x, v1 = a.y + g.y, v2 = a.z + g.z, v3 = a.w + g.w;
        float s = v0 + v1 + v2 + v3;
#pragma unroll
        for (int o = 16; o; o >>= 1) s += __shfl_xor_sync(0xffffffffu, s, o);
        float mu = s * (1.f / 128.f);
        float d0 = v0 - mu, d1 = v1 - mu, d2 = v2 - mu, d3 = v3 - mu;
        float q = d0 * d0 + d1 * d1 + d2 * d2 + d3 * d3;
#pragma unroll
        for (int o = 16; o; o >>= 1) q += __shfl_xor_sync(0xffffffffu, q, o);
        float rs = rsqrtf(q * (1.f / 128.f) + 1e-5f);
        H1sh[r * 132 + c0 + 0] = d0 * rs * g1[c0 + 0] + b1[c0 + 0];
        H1sh[r * 132 + c0 + 1] = d1 * rs * g1[c0 + 1] + b1[c0 + 1];
        H1sh[r * 132 + c0 + 2] = d2 * rs * g1[c0 + 2] + b1[c0 + 2];
        H1sh[r * 132 + c0 + 3] = d3 * rs * g1[c0 + 3] + b1[c0 + 3];
    }

    const int tc = tid & 15, tr = tid >> 4;

    // step 2: FF1 (128 -> 512) in 4 column chunks, gelu -> Tsh
    for (int nc = 0; nc < 4; nc++) {
        __syncthreads();
        for (int i = tid; i < 4096; i += 256) {
            int k = i >> 5, c4 = i & 31;
            ((float4*)&Wsh[k * 128])[c4] = ((const float4*)&fW1[(size_t)k * 512 + nc * 128])[c4];
        }
        __syncthreads();
        float acc[2][8];
#pragma unroll
        for (int i = 0; i < 2; i++)
#pragma unroll
            for (int j = 0; j < 8; j++) acc[i][j] = fb1[nc * 128 + tc * 8 + j];
#pragma unroll 4
        for (int kk = 0; kk < 128; kk++) {
            float4 b0 = *(const float4*)&Wsh[kk * 128 + tc * 8];
            float4 b1v = *(const float4*)&Wsh[kk * 128 + tc * 8 + 4];
#pragma unroll
            for (int i = 0; i < 2; i++) {
                float a = H1sh[(tr * 2 + i) * 132 + kk];
                acc[i][0] = fmaf(a, b0.x, acc[i][0]);
                acc[i][1] = fmaf(a, b0.y, acc[i][1]);
                acc[i][2] = fmaf(a, b0.z, acc[i][2]);
                acc[i][3] = fmaf(a, b0.w, acc[i][3]);
                acc[i][4] = fmaf(a, b1v.x, acc[i][4]);
                acc[i][5] = fmaf(a, b1v.y, acc[i][5]);
                acc[i][6] = fmaf(a, b1v.z, acc[i][6]);
                acc[i][7] = fmaf(a, b1v.w, acc[i][7]);
            }
        }
#pragma unroll
        for (int i = 0; i < 2; i++)
#pragma unroll
            for (int j = 0; j < 8; j++)
                Tsh[(tr * 2 + i) * 516 + nc * 128 + tc * 8 + j] = gelu_exact(acc[i][j]);
    }

    // step 3: FF2 (512 -> 128), K streamed in 4 chunks
    float acc2[2][8];
#pragma unroll
    for (int i = 0; i < 2; i++)
#pragma unroll
        for (int j = 0; j < 8; j++) acc2[i][j] = fb2[tc * 8 + j];
    for (int kc = 0; kc < 4; kc++) {
        __syncthreads();
        for (int i = tid; i < 4096; i += 256) {
            int k = i >> 5, c4 = i & 31;
            ((float4*)&Wsh[k * 128])[c4] = ((const float4*)&fW2[(size_t)(kc * 128 + k) * 128])[c4];
        }
        __syncthreads();
#pragma unroll 4
        for (int kk = 0; kk < 128; kk++) {
            float4 b0 = *(const float4*)&Wsh[kk * 128 + tc * 8];
            float4 b1v = *(const float4*)&Wsh[kk * 128 + tc * 8 + 4];
#pragma unroll
            for (int i = 0; i < 2; i++) {
                float a = Tsh[(tr * 2 + i) * 516 + kc * 128 + kk];
                acc2[i][0] = fmaf(a, b0.x, acc2[i][0]);
                acc2[i][1] = fmaf(a, b0.y, acc2[i][1]);
                acc2[i][2] = fmaf(a, b0.z, acc2[i][2]);
                acc2[i][3] = fmaf(a, b0.w, acc2[i][3]);
                acc2[i][4] = fmaf(a, b1v.x, acc2[i][4]);
                acc2[i][5] = fmaf(a, b1v.y, acc2[i][5]);
                acc2[i][6] = fmaf(a, b1v.z, acc2[i][6]);
                acc2[i][7] = fmaf(a, b1v.w, acc2[i][7]);
            }
        }
    }

    // step 4: v = h1 + ff -> LN2 -> out.  Reuse Tsh front as padded V buffer.
    __syncthreads();
    float* Vsh = Tsh;  // 32*132 region
#pragma unroll
    for (int i = 0; i < 2; i++)
#pragma unroll
        for (int j = 0; j < 8; j++) {
            int r = tr * 2 + i, c = tc * 8 + j;
            Vsh[r * 132 + c] = H1sh[r * 132 + c] + acc2[i][j];
        }
    __syncthreads();
    for (int r = wid; r < 32; r += 8) {
        const int c0 = lane * 4;
        float v0 = Vsh[r * 132 + c0 + 0], v1 = Vsh[r * 132 + c0 + 1];
        float v2 = Vsh[r * 132 + c0 + 2], v3 = Vsh[r * 132 + c0 + 3];
        float s = v0 + v1 + v2 + v3;
#pragma unroll
        for (int o = 16; o; o >>= 1) s += __shfl_xor_sync(0xffffffffu, s, o);
        float mu = s * (1.f / 128.f);
        float d0 = v0 - mu, d1 = v1 - mu, d2 = v2 - mu, d3 = v3 - mu;
        float q = d0 * d0 + d1 * d1 + d2 * d2 + d3 * d3;
#pragma unroll
        for (int o = 16; o; o >>= 1) q += __shfl_xor_sync(0xffffffffu, q, o);
        float rs = rsqrtf(q * (1.f / 128.f) + 1e-5f);
        float4 o4;
        o4.x = d0 * rs * g2[c0 + 0] + b2[c0 + 0];
        o4.y = d1 * rs * g2[c0 + 1] + b2[c0 + 1];
        o4.z = d2 * rs * g2[c0 + 2] + b2[c0 + 2];
        o4.w = d3 * rs * g2[c0 + 3] + b2[c0 + 3];
        *(float4*)&out[(size_t)(m0 + r) * NH + c0] = o4;
    }
}

// ---------------------------------------------------------------------------
extern "C" void kernel_launch(void* const* d_in, const int* in_sizes, int n_in,
                              void* d_out, int out_size) {
    const float* node_h   = (const float*)d_in[0];
    const float* edge_h   = (const float*)d_in[1];
    const int*   edge_idx = (const int*)d_in[2];
    const float* seq_emb  = (const float*)d_in[3];
    const float* ar_mask  = (const float*)d_in[4];
    const float* mW1 = (const float*)d_in[5];
    const float* mb1 = (const float*)d_in[6];
    const float* mW2 = (const float*)d_in[7];
    const float* mb2 = (const float*)d_in[8];
    const float* mW3 = (const float*)d_in[9];
    const float* mb3 = (const float*)d_in[10];
    const float* fW1 = (const float*)d_in[11];
    const float* fb1 = (const float*)d_in[12];
    const float* fW2 = (const float*)d_in[13];
    const float* fb2 = (const float*)d_in[14];
    const float* g1  = (const float*)d_in[15];
    const float* b1  = (const float*)d_in[16];
    const float* g2  = (const float*)d_in[17];
    const float* b2  = (const float*)d_in[18];
    float* out = (float*)d_out;

    int dev = 0;
    cudaGetDevice(&dev);
    int nsm = 148;
    cudaDeviceGetAttribute(&nsm, cudaDevAttrMultiProcessorCount, dev);

    const size_t smem1 = (size_t)(16384 + 64 * 132) * sizeof(float);            // ~97 KB
    const size_t smem2 = (size_t)(16384 + 16384 + 96 * 132 + 256) * sizeof(float); // ~178.5 KB
    const size_t smem3 = (size_t)(32 * 132 + 32 * 516 + 16384) * sizeof(float);  // ~145 KB

    cudaFuncSetAttribute(k1_pre, cudaFuncAttributeMaxDynamicSharedMemorySize, (int)smem1);
    cudaFuncSetAttribute(k2_msg, cudaFuncAttributeMaxDynamicSharedMemorySize, (int)smem2);
    cudaFuncSetAttribute(k3_ff,  cudaFuncAttributeMaxDynamicSharedMemorySize, (int)smem3);

    dim3 grid1(NRES / 64, 3);
    k1_pre<<<grid1, 256, smem1>>>(node_h, seq_emb, mW1);

    k2_msg<<<nsm, 256, smem2>>>(edge_h, edge_idx, ar_mask,
                                mW1, mb1, mW2, mb2, mW3, mb3, NRES / 2);

    k3_ff<<<NRES / 32, 256, smem3>>>(node_h, fW1, fb1, fW2, fb2,
                                     g1, b1, g2, b2, out);
}

// round 4
// speedup vs baseline: 1.2181x; 1.2181x over previous
#include <cuda_runtime.h>
#include <cuda_bf16.h>
#include <math.h>
#include <stdint.h>

#define NRES 8192
#define NK   48
#define NH   128

__device__ float g_Pi[NRES * NH];
__device__ float g_Pj[NRES * NH];
__device__ float g_Ps[NRES * NH];
__device__ float g_S [NRES * NH];

__device__ __forceinline__ float gelu_exact(float x) {
    return 0.5f * x * (1.0f + erff(x * 0.7071067811865475f));
}
__device__ __forceinline__ uint32_t smem_u32(const void* p) {
    uint32_t a;
    asm("{ .reg .u64 t; cvta.to.shared.u64 t, %1; cvt.u32.u64 %0, t; }" : "=r"(a) : "l"(p));
    return a;
}
__device__ __forceinline__ uint32_t pack_bf(__nv_bfloat16 a, __nv_bfloat16 b) {
    return (uint32_t)__bfloat16_as_ushort(a) | ((uint32_t)__bfloat16_as_ushort(b) << 16);
}
__device__ __forceinline__ void split_bf(float x, __nv_bfloat16& h, __nv_bfloat16& l) {
    h = __float2bfloat16(x);
    l = __float2bfloat16(x - __bfloat162float(h));
}
__device__ __forceinline__ void ldm_x4(uint32_t& r0, uint32_t& r1, uint32_t& r2, uint32_t& r3, uint32_t a) {
    asm volatile("ldmatrix.sync.aligned.m8n8.x4.shared.b16 {%0,%1,%2,%3}, [%4];"
                 : "=r"(r0), "=r"(r1), "=r"(r2), "=r"(r3) : "r"(a));
}
__device__ __forceinline__ void ldm_x2(uint32_t& r0, uint32_t& r1, uint32_t a) {
    asm volatile("ldmatrix.sync.aligned.m8n8.x2.shared.b16 {%0,%1}, [%2];"
                 : "=r"(r0), "=r"(r1) : "r"(a));
}
__device__ __forceinline__ void mma_bf16(float* c, uint32_t a0, uint32_t a1, uint32_t a2, uint32_t a3,
                                         uint32_t b0, uint32_t b1) {
    asm volatile("mma.sync.aligned.m16n8k16.row.col.f32.bf16.bf16.f32 "
                 "{%0,%1,%2,%3}, {%4,%5,%6,%7}, {%8,%9}, {%0,%1,%2,%3};"
                 : "+f"(c[0]), "+f"(c[1]), "+f"(c[2]), "+f"(c[3])
                 : "r"(a0), "r"(a1), "r"(a2), "r"(a3), "r"(b0), "r"(b1));
}

// ---------------------------------------------------------------------------
// Kernel 1: Pi/Pj/Ps per-residue projections (fp32 CUDA-core)
// ---------------------------------------------------------------------------
__global__ __launch_bounds__(256) void k1_pre(const float* __restrict__ node_h,
                                              const float* __restrict__ seq_emb,
                                              const float* __restrict__ mW1) {
    extern __shared__ float sm1[];
    float* Wsh = sm1;
    float* Ash = sm1 + 16384;
    const int tid   = threadIdx.x;
    const int which = blockIdx.y;
    const float* A    = (which == 2) ? seq_emb : node_h;
    const float* Wsrc = mW1 + (size_t)(which == 0 ? 0 : (which == 1 ? 128 : 384)) * NH;
    float* out = (which == 0) ? g_Pi : (which == 1 ? g_Pj : g_Ps);

    for (int i = tid; i < 4096; i += 256) ((float4*)Wsh)[i] = ((const float4*)Wsrc)[i];
    const int m0 = blockIdx.x * 64;
    for (int i = tid; i < 2048; i += 256) {
        int r = i >> 5, c4 = i & 31;
        *(float4*)&Ash[r * 132 + c4 * 4] = ((const float4*)(A + (size_t)(m0 + r) * NH))[c4];
    }
    __syncthreads();
    const int tc = tid & 15, tr = tid >> 4;
    float acc[4][8];
#pragma unroll
    for (int i = 0; i < 4; i++)
#pragma unroll
        for (int j = 0; j < 8; j++) acc[i][j] = 0.f;
#pragma unroll 4
    for (int kk = 0; kk < 128; kk++) {
        float4 b0 = *(const float4*)&Wsh[kk * 128 + tc * 8];
        float4 b1 = *(const float4*)&Wsh[kk * 128 + tc * 8 + 4];
#pragma unroll
        for (int i = 0; i < 4; i++) {
            float a = Ash[(tr * 4 + i) * 132 + kk];
            acc[i][0] = fmaf(a, b0.x, acc[i][0]); acc[i][1] = fmaf(a, b0.y, acc[i][1]);
            acc[i][2] = fmaf(a, b0.z, acc[i][2]); acc[i][3] = fmaf(a, b0.w, acc[i][3]);
            acc[i][4] = fmaf(a, b1.x, acc[i][4]); acc[i][5] = fmaf(a, b1.y, acc[i][5]);
            acc[i][6] = fmaf(a, b1.z, acc[i][6]); acc[i][7] = fmaf(a, b1.w, acc[i][7]);
        }
    }
#pragma unroll
    for (int i = 0; i < 4; i++) {
        size_t r = (size_t)(m0 + tr * 4 + i) * NH + tc * 8;
#pragma unroll
        for (int j = 0; j < 8; j++) out[r + j] = acc[i][j];
    }
}

// ---------------------------------------------------------------------------
// Kernel 2: per-edge MLP via mma.sync (bf16 3-pass split) + aggregation
// Tile M=64 edges, N=128, K=128. 8 warps in 2(M) x 4(N). Group = 192 edges.
// ---------------------------------------------------------------------------
// byte offsets into dynamic smem
#define S_BT1H 0u
#define S_BT1L 34816u
#define S_BT2H 69632u
#define S_BT2L 104448u
#define S_AH   139264u
#define S_AL   156672u
#define S_BASE 174080u   // 64 x 132 fp32 (aliased with X2)
#define S_SSUM 207872u   // 4 x 128 fp32
#define S_MB1  209920u   // 128 fp32
#define S_K2TOT 210432u
#define LDB 272u         // operand row stride in bytes (136 bf16)

__global__ __launch_bounds__(256) void k2_msg(const float* __restrict__ edge_h,
                                              const int*   __restrict__ edge_idx,
                                              const float* __restrict__ ar_mask,
                                              const float* __restrict__ mW1,
                                              const float* __restrict__ mb1,
                                              const float* __restrict__ mW2,
                                              const float* __restrict__ mb2,
                                              int ngroups) {
    extern __shared__ char sm[];
    const int tid  = threadIdx.x;
    const int w    = tid >> 5, lane = tid & 31;
    const int gid  = lane >> 2, t4 = lane & 3;
    const int wm   = w >> 2, wn = w & 3;         // warp grid 2 x 4
    const int m_base = wm * 32, n_base = wn * 32;
    const uint32_t sb = smem_u32(sm);

    float* BASE = (float*)(sm + S_BASE);          // stride 132 floats
    float* X2sh = BASE;                           // alias
    float* SSUM = (float*)(sm + S_SSUM);
    float* MB1  = (float*)(sm + S_MB1);

    // ---- one-time staging: weights as BT[n][k] bf16 hi/lo, mb1 ----
    if (tid < 128) MB1[tid] = mb1[tid];
    for (int idx = tid; idx < 16384; idx += 256) {
        const int n = idx >> 7, k = idx & 127;
        float w1 = mW1[(size_t)(256 + k) * NH + n];
        float w2 = mW2[(size_t)k * NH + n];
        __nv_bfloat16 h1, l1, h2, l2;
        split_bf(w1, h1, l1); split_bf(w2, h2, l2);
        const uint32_t o = (uint32_t)n * LDB + (uint32_t)k * 2u;
        *(unsigned short*)(sm + S_BT1H + o) = __bfloat16_as_ushort(h1);
        *(unsigned short*)(sm + S_BT1L + o) = __bfloat16_as_ushort(l1);
        *(unsigned short*)(sm + S_BT2H + o) = __bfloat16_as_ushort(h2);
        *(unsigned short*)(sm + S_BT2L + o) = __bfloat16_as_ushort(l2);
    }

    // per-lane mb2 pairs (GEMM2 acc init)
    float2 mb2v[4];
#pragma unroll
    for (int j = 0; j < 4; j++)
        mb2v[j] = *(const float2*)&mb2[n_base + j * 8 + t4 * 2];

    // lane-fixed ldmatrix base addresses
    // A: lanes 0-15 -> rows 0..15 (khalf 0), lanes 16-31 -> rows 0..15 (khalf 1)
    const uint32_t a_row  = (uint32_t)(m_base + (lane & 15));
    const uint32_t a_koff = (uint32_t)((lane >> 4) * 16);     // bytes (8 bf16)
    const uint32_t aH0 = sb + S_AH + a_row * LDB + a_koff;    // matom 0
    const uint32_t aL0 = sb + S_AL + a_row * LDB + a_koff;
    // B: lanes 0-7 khalf0, lanes 8-15 khalf1 (x2 uses lanes 0-15)
    const uint32_t b_row  = (uint32_t)((lane & 7));
    const uint32_t b_koff = (uint32_t)(((lane >> 3) & 1) * 16);
    uint32_t bBase[4];
#pragma unroll
    for (int j = 0; j < 4; j++)
        bBase[j] = (uint32_t)(n_base + j * 8 + b_row) * LDB + b_koff;

    for (int g = blockIdx.x; g < ngroups; g += gridDim.x) {
        __syncthreads();
        for (int i = tid; i < 512; i += 256) SSUM[i] = 0.f;

        for (int t = 0; t < 3; t++) {
            const int row0 = g * 192 + t * 64;
            __syncthreads();   // SSUM zero / prev segsum reads done

            // ---- build E -> AH/AL and BASE tile ----
            {
                const int r = tid >> 2, q = tid & 3;         // row 0..63, col-quarter
                const int grow = row0 + r;
                const int res  = grow / NK;
                const int nbr  = edge_idx[grow];
                const float am = ar_mask[grow];
                const float4* E4  = (const float4*)(edge_h + (size_t)grow * NH);
                const float4* Pi4 = (const float4*)(g_Pi + (size_t)res * NH);
                const float4* Pj4 = (const float4*)(g_Pj + (size_t)nbr * NH);
                const float4* Ps4 = (const float4*)(g_Ps + (size_t)nbr * NH);
                const float4* M14 = (const float4*)MB1;
#pragma unroll
                for (int c8 = 0; c8 < 8; c8++) {
                    const int c4 = q * 8 + c8;               // float4 index (col = c4*4)
                    float4 e = E4[c4];
                    __nv_bfloat16 h0, l0, h1, l1, h2, l2, h3, l3;
                    split_bf(e.x, h0, l0); split_bf(e.y, h1, l1);
                    split_bf(e.z, h2, l2); split_bf(e.w, h3, l3);
                    const uint32_t o = (uint32_t)r * LDB + (uint32_t)c4 * 8u;
                    *(uint2*)(sm + S_AH + o) = make_uint2(pack_bf(h0, h1), pack_bf(h2, h3));
                    *(uint2*)(sm + S_AL + o) = make_uint2(pack_bf(l0, l1), pack_bf(l2, l3));
                    float4 a = Pi4[c4], b = Pj4[c4], c = Ps4[c4], m = M14[c4];
                    float4 v;
                    v.x = a.x + b.x + am * c.x + m.x;
                    v.y = a.y + b.y + am * c.y + m.y;
                    v.z = a.z + b.z + am * c.z + m.z;
                    v.w = a.w + b.w + am * c.w + m.w;
                    *(float4*)&BASE[r * 132 + c4 * 4] = v;
                }
            }
            __syncthreads();

            float acc[2][4][4];

            // ---- GEMM1: acc = BASE + E @ W1c ----
#pragma unroll
            for (int i = 0; i < 2; i++) {
                const int m_e = m_base + i * 16 + gid;
#pragma unroll
                for (int j = 0; j < 4; j++) {
                    const int n_e = n_base + j * 8 + t4 * 2;
                    float2 lo = *(float2*)&BASE[m_e * 132 + n_e];
                    float2 hi = *(float2*)&BASE[(m_e + 8) * 132 + n_e];
                    acc[i][j][0] = lo.x; acc[i][j][1] = lo.y;
                    acc[i][j][2] = hi.x; acc[i][j][3] = hi.y;
                }
            }
#pragma unroll
            for (int ks = 0; ks < 8; ks++) {
                const uint32_t ko = (uint32_t)ks * 32u;
                uint32_t ah[2][4], al[2][4], bh[4][2], bl[4][2];
#pragma unroll
                for (int i = 0; i < 2; i++) {
                    ldm_x4(ah[i][0], ah[i][1], ah[i][2], ah[i][3], aH0 + (uint32_t)i * 16u * LDB + ko);
                    ldm_x4(al[i][0], al[i][1], al[i][2], al[i][3], aL0 + (uint32_t)i * 16u * LDB + ko);
                }
#pragma unroll
                for (int j = 0; j < 4; j++) {
                    ldm_x2(bh[j][0], bh[j][1], sb + S_BT1H + bBase[j] + ko);
                    ldm_x2(bl[j][0], bl[j][1], sb + S_BT1L + bBase[j] + ko);
                }
#pragma unroll
                for (int i = 0; i < 2; i++)
#pragma unroll
                    for (int j = 0; j < 4; j++) {
                        mma_bf16(acc[i][j], ah[i][0], ah[i][1], ah[i][2], ah[i][3], bh[j][0], bh[j][1]);
                        mma_bf16(acc[i][j], al[i][0], al[i][1], al[i][2], al[i][3], bh[j][0], bh[j][1]);
                        mma_bf16(acc[i][j], ah[i][0], ah[i][1], ah[i][2], ah[i][3], bl[j][0], bl[j][1]);
                    }
            }
            __syncthreads();   // all GEMM1 reads of AH/AL done

            // ---- epilogue 1: X1 = gelu(acc) -> AH/AL ----
#pragma unroll
            for (int i = 0; i < 2; i++) {
                const int m_e = m_base + i * 16 + gid;
#pragma unroll
                for (int j = 0; j < 4; j++) {
                    const int n_e = n_base + j * 8 + t4 * 2;
                    float v0 = gelu_exact(acc[i][j][0]), v1 = gelu_exact(acc[i][j][1]);
                    float v2 = gelu_exact(acc[i][j][2]), v3 = gelu_exact(acc[i][j][3]);
                    __nv_bfloat16 h0, l0, h1, l1, h2, l2, h3, l3;
                    split_bf(v0, h0, l0); split_bf(v1, h1, l1);
                    split_bf(v2, h2, l2); split_bf(v3, h3, l3);
                    const uint32_t o0 = (uint32_t)m_e * LDB + (uint32_t)n_e * 2u;
                    const uint32_t o1 = o0 + 8u * LDB;
                    *(uint32_t*)(sm + S_AH + o0) = pack_bf(h0, h1);
                    *(uint32_t*)(sm + S_AL + o0) = pack_bf(l0, l1);
                    *(uint32_t*)(sm + S_AH + o1) = pack_bf(h2, h3);
                    *(uint32_t*)(sm + S_AL + o1) = pack_bf(l2, l3);
                }
            }
            __syncthreads();

            // ---- GEMM2: acc = mb2 + X1 @ W2 ----
#pragma unroll
            for (int i = 0; i < 2; i++)
#pragma unroll
                for (int j = 0; j < 4; j++) {
                    acc[i][j][0] = mb2v[j].x; acc[i][j][1] = mb2v[j].y;
                    acc[i][j][2] = mb2v[j].x; acc[i][j][3] = mb2v[j].y;
                }
#pragma unroll
            for (int ks = 0; ks < 8; ks++) {
                const uint32_t ko = (uint32_t)ks * 32u;
                uint32_t ah[2][4], al[2][4], bh[4][2], bl[4][2];
#pragma unroll
                for (int i = 0; i < 2; i++) {
                    ldm_x4(ah[i][0], ah[i][1], ah[i][2], ah[i][3], aH0 + (uint32_t)i * 16u * LDB + ko);
                    ldm_x4(al[i][0], al[i][1], al[i][2], al[i][3], aL0 + (uint32_t)i * 16u * LDB + ko);
                }
#pragma unroll
                for (int j = 0; j < 4; j++) {
                    ldm_x2(bh[j][0], bh[j][1], sb + S_BT2H + bBase[j] + ko);
                    ldm_x2(bl[j][0], bl[j][1], sb + S_BT2L + bBase[j] + ko);
                }
#pragma unroll
                for (int i = 0; i < 2; i++)
#pragma unroll
                    for (int j = 0; j < 4; j++) {
                        mma_bf16(acc[i][j], ah[i][0], ah[i][1], ah[i][2], ah[i][3], bh[j][0], bh[j][1]);
                        mma_bf16(acc[i][j], al[i][0], al[i][1], al[i][2], al[i][3], bh[j][0], bh[j][1]);
                        mma_bf16(acc[i][j], ah[i][0], ah[i][1], ah[i][2], ah[i][3], bl[j][0], bl[j][1]);
                    }
            }

            // ---- epilogue 2: X2 = gelu(acc) -> X2sh (fp32, aliases BASE) ----
#pragma unroll
            for (int i = 0; i < 2; i++) {
                const int m_e = m_base + i * 16 + gid;
#pragma unroll
                for (int j = 0; j < 4; j++) {
                    const int n_e = n_base + j * 8 + t4 * 2;
                    float2 lo, hi;
                    lo.x = gelu_exact(acc[i][j][0]); lo.y = gelu_exact(acc[i][j][1]);
                    hi.x = gelu_exact(acc[i][j][2]); hi.y = gelu_exact(acc[i][j][3]);
                    *(float2*)&X2sh[m_e * 132 + n_e]       = lo;
                    *(float2*)&X2sh[(m_e + 8) * 132 + n_e] = hi;
                }
            }
            __syncthreads();

            // ---- segmented column sums (48-edge residues) ----
            {
                const int col = tid & 127, part = tid >> 7;
                const int gr0 = t * 64;
                const int rl_lo = gr0 / 48, rl_hi = (gr0 + 63) / 48;
                for (int rl = rl_lo; rl <= rl_hi; rl++) {
                    int lo = rl * 48 - gr0;      if (lo < 0) lo = 0;
                    int hi = rl * 48 + 48 - gr0; if (hi > 64) hi = 64;
                    float s = 0.f;
                    for (int r = lo + part; r < hi; r += 2) s += X2sh[r * 132 + col];
                    atomicAdd(&SSUM[rl * 128 + col], s);
                }
            }
        }
        __syncthreads();
        for (int i = tid; i < 512; i += 256)
            g_S[(size_t)g * 512 + i] = SSUM[i];
    }
}

// ---------------------------------------------------------------------------
// Kernel 3: agg = S@W3 + 48*mb3; LN1; FFN; LN2 -> out (32 residues/CTA)
// ---------------------------------------------------------------------------
__global__ __launch_bounds__(256) void k3_ff(const float* __restrict__ node_h,
                                             const float* __restrict__ mW3,
                                             const float* __restrict__ mb3,
                                             const float* __restrict__ fW1,
                                             const float* __restrict__ fb1,
                                             const float* __restrict__ fW2,
                                             const float* __restrict__ fb2,
                                             const float* __restrict__ g1,
                                             const float* __restrict__ b1,
                                             const float* __restrict__ g2,
                                             const float* __restrict__ b2,
                                             float* __restrict__ out) {
    extern __shared__ float sm3[];
    float* H1sh = sm3;                        // 32*132
    float* Tsh  = sm3 + 32 * 132;             // 32*516
    float* Wsh  = sm3 + 32 * 132 + 32 * 516;  // 128*128

    const int tid = threadIdx.x;
    const int wid = tid >> 5, lane = tid & 31;
    const int m0  = blockIdx.x * 32;
    const int tc = tid & 15, tr = tid >> 4;

    for (int i = tid; i < 4096; i += 256) ((float4*)Wsh)[i] = ((const float4*)mW3)[i];
    for (int i = tid; i < 1024; i += 256) {
        int r = i >> 5, c4 = i & 31;
        *(float4*)&Tsh[r * 132 + c4 * 4] = ((const float4*)(g_S + (size_t)(m0 + r) * NH))[c4];
    }
    __syncthreads();

    {
        float acc[2][8];
#pragma unroll
        for (int i = 0; i < 2; i++)
#pragma unroll
            for (int j = 0; j < 8; j++) acc[i][j] = 48.f * mb3[tc * 8 + j];
#pragma unroll 4
        for (int kk = 0; kk < 128; kk++) {
            float4 b0 = *(const float4*)&Wsh[kk * 128 + tc * 8];
            float4 b1v = *(const float4*)&Wsh[kk * 128 + tc * 8 + 4];
#pragma unroll
            for (int i = 0; i < 2; i++) {
                float a = Tsh[(tr * 2 + i) * 132 + kk];
                acc[i][0] = fmaf(a, b0.x, acc[i][0]); acc[i][1] = fmaf(a, b0.y, acc[i][1]);
                acc[i][2] = fmaf(a, b0.z, acc[i][2]); acc[i][3] = fmaf(a, b0.w, acc[i][3]);
                acc[i][4] = fmaf(a, b1v.x, acc[i][4]); acc[i][5] = fmaf(a, b1v.y, acc[i][5]);
                acc[i][6] = fmaf(a, b1v.z, acc[i][6]); acc[i][7] = fmaf(a, b1v.w, acc[i][7]);
            }
        }
#pragma unroll
        for (int i = 0; i < 2; i++) {
            const float* nrow = node_h + (size_t)(m0 + tr * 2 + i) * NH + tc * 8;
            float4 n0 = *(const float4*)nrow, n1 = *(const float4*)(nrow + 4);
            float* hrow = &H1sh[(tr * 2 + i) * 132 + tc * 8];
            hrow[0] = acc[i][0] + n0.x; hrow[1] = acc[i][1] + n0.y;
            hrow[2] = acc[i][2] + n0.z; hrow[3] = acc[i][3] + n0.w;
            hrow[4] = acc[i][4] + n1.x; hrow[5] = acc[i][5] + n1.y;
            hrow[6] = acc[i][6] + n1.z; hrow[7] = acc[i][7] + n1.w;
        }
    }
    __syncthreads();

    for (int r = wid; r < 32; r += 8) {
        const int c0 = lane * 4;
        float v0 = H1sh[r * 132 + c0], v1 = H1sh[r * 132 + c0 + 1];
        float v2 = H1sh[r * 132 + c0 + 2], v3 = H1sh[r * 132 + c0 + 3];
        float s = v0 + v1 + v2 + v3;
#pragma unroll
        for (int o = 16; o; o >>= 1) s += __shfl_xor_sync(0xffffffffu, s, o);
        float mu = s * (1.f / 128.f);
        float d0 = v0 - mu, d1 = v1 - mu, d2 = v2 - mu, d3 = v3 - mu;
        float q = d0 * d0 + d1 * d1 + d2 * d2 + d3 * d3;
#pragma unroll
        for (int o = 16; o; o >>= 1) q += __shfl_xor_sync(0xffffffffu, q, o);
        float rs = rsqrtf(q * (1.f / 128.f) + 1e-5f);
        H1sh[r * 132 + c0]     = d0 * rs * g1[c0]     + b1[c0];
        H1sh[r * 132 + c0 + 1] = d1 * rs * g1[c0 + 1] + b1[c0 + 1];
        H1sh[r * 132 + c0 + 2] = d2 * rs * g1[c0 + 2] + b1[c0 + 2];
        H1sh[r * 132 + c0 + 3] = d3 * rs * g1[c0 + 3] + b1[c0 + 3];
    }

    for (int nc = 0; nc < 4; nc++) {
        __syncthreads();
        for (int i = tid; i < 4096; i += 256) {
            int k = i >> 5, c4 = i & 31;
            ((float4*)&Wsh[k * 128])[c4] = ((const float4*)&fW1[(size_t)k * 512 + nc * 128])[c4];
        }
        __syncthreads();
        float acc[2][8];
#pragma unroll
        for (int i = 0; i < 2; i++)
#pragma unroll
            for (int j = 0; j < 8; j++) acc[i][j] = fb1[nc * 128 + tc * 8 + j];
#pragma unroll 4
        for (int kk = 0; kk < 128; kk++) {
            float4 b0 = *(const float4*)&Wsh[kk * 128 + tc * 8];
            float4 b1v = *(const float4*)&Wsh[kk * 128 + tc * 8 + 4];
#pragma unroll
            for (int i = 0; i < 2; i++) {
                float a = H1sh[(tr * 2 + i) * 132 + kk];
                acc[i][0] = fmaf(a, b0.x, acc[i][0]); acc[i][1] = fmaf(a, b0.y, acc[i][1]);
                acc[i][2] = fmaf(a, b0.z, acc[i][2]); acc[i][3] = fmaf(a, b0.w, acc[i][3]);
                acc[i][4] = fmaf(a, b1v.x, acc[i][4]); acc[i][5] = fmaf(a, b1v.y, acc[i][5]);
                acc[i][6] = fmaf(a, b1v.z, acc[i][6]); acc[i][7] = fmaf(a, b1v.w, acc[i][7]);
            }
        }
#pragma unroll
        for (int i = 0; i < 2; i++)
#pragma unroll
            for (int j = 0; j < 8; j++)
                Tsh[(tr * 2 + i) * 516 + nc * 128 + tc * 8 + j] = gelu_exact(acc[i][j]);
    }

    float acc2[2][8];
#pragma unroll
    for (int i = 0; i < 2; i++)
#pragma unroll
        for (int j = 0; j < 8; j++) acc2[i][j] = fb2[tc * 8 + j];
    for (int kc = 0; kc < 4; kc++) {
        __syncthreads();
        for (int i = tid; i < 4096; i += 256) {
            int k = i >> 5, c4 = i & 31;
            ((float4*)&Wsh[k * 128])[c4] = ((const float4*)&fW2[(size_t)(kc * 128 + k) * 128])[c4];
        }
        __syncthreads();
#pragma unroll 4
        for (int kk = 0; kk < 128; kk++) {
            float4 b0 = *(const float4*)&Wsh[kk * 128 + tc * 8];
            float4 b1v = *(const float4*)&Wsh[kk * 128 + tc * 8 + 4];
#pragma unroll
            for (int i = 0; i < 2; i++) {
                float a = Tsh[(tr * 2 + i) * 516 + kc * 128 + kk];
                acc2[i][0] = fmaf(a, b0.x, acc2[i][0]); acc2[i][1] = fmaf(a, b0.y, acc2[i][1]);
                acc2[i][2] = fmaf(a, b0.z, acc2[i][2]); acc2[i][3] = fmaf(a, b0.w, acc2[i][3]);
                acc2[i][4] = fmaf(a, b1v.x, acc2[i][4]); acc2[i][5] = fmaf(a, b1v.y, acc2[i][5]);
                acc2[i][6] = fmaf(a, b1v.z, acc2[i][6]); acc2[i][7] = fmaf(a, b1v.w, acc2[i][7]);
            }
        }
    }

    __syncthreads();
    float* Vsh = Tsh;
#pragma unroll
    for (int i = 0; i < 2; i++)
#pragma unroll
        for (int j = 0; j < 8; j++) {
            int r = tr * 2 + i, c = tc * 8 + j;
            Vsh[r * 132 + c] = H1sh[r * 132 + c] + acc2[i][j];
        }
    __syncthreads();
    for (int r = wid; r < 32; r += 8) {
        const int c0 = lane * 4;
        float v0 = Vsh[r * 132 + c0], v1 = Vsh[r * 132 + c0 + 1];
        float v2 = Vsh[r * 132 + c0 + 2], v3 = Vsh[r * 132 + c0 + 3];
        float s = v0 + v1 + v2 + v3;
#pragma unroll
        for (int o = 16; o; o >>= 1) s += __shfl_xor_sync(0xffffffffu, s, o);
        float mu = s * (1.f / 128.f);
        float d0 = v0 - mu, d1 = v1 - mu, d2 = v2 - mu, d3 = v3 - mu;
        float q = d0 * d0 + d1 * d1 + d2 * d2 + d3 * d3;
#pragma unroll
        for (int o = 16; o; o >>= 1) q += __shfl_xor_sync(0xffffffffu, q, o);
        float rs = rsqrtf(q * (1.f / 128.f) + 1e-5f);
        float4 o4;
        o4.x = d0 * rs * g2[c0]     + b2[c0];
        o4.y = d1 * rs * g2[c0 + 1] + b2[c0 + 1];
        o4.z = d2 * rs * g2[c0 + 2] + b2[c0 + 2];
        o4.w = d3 * rs * g2[c0 + 3] + b2[c0 + 3];
        *(float4*)&out[(size_t)(m0 + r) * NH + c0] = o4;
    }
}

// ---------------------------------------------------------------------------
extern "C" void kernel_launch(void* const* d_in, const int* in_sizes, int n_in,
                              void* d_out, int out_size) {
    const float* node_h   = (const float*)d_in[0];
    const float* edge_h   = (const float*)d_in[1];
    const int*   edge_idx = (const int*)d_in[2];
    const float* seq_emb  = (const float*)d_in[3];
    const float* ar_mask  = (const float*)d_in[4];
    const float* mW1 = (const float*)d_in[5];
    const float* mb1 = (const float*)d_in[6];
    const float* mW2 = (const float*)d_in[7];
    const float* mb2 = (const float*)d_in[8];
    const float* mW3 = (const float*)d_in[9];
    const float* mb3 = (const float*)d_in[10];
    const float* fW1 = (const float*)d_in[11];
    const float* fb1 = (const float*)d_in[12];
    const float* fW2 = (const float*)d_in[13];
    const float* fb2 = (const float*)d_in[14];
    const float* g1  = (const float*)d_in[15];
    const float* b1  = (const float*)d_in[16];
    const float* g2  = (const float*)d_in[17];
    const float* b2  = (const float*)d_in[18];
    float* out = (float*)d_out;

    int dev = 0;
    cudaGetDevice(&dev);
    int nsm = 148;
    cudaDeviceGetAttribute(&nsm, cudaDevAttrMultiProcessorCount, dev);

    const size_t smem1 = (size_t)(16384 + 64 * 132) * sizeof(float);
    const size_t smem3 = (size_t)(32 * 132 + 32 * 516 + 16384) * sizeof(float);

    cudaFuncSetAttribute(k1_pre, cudaFuncAttributeMaxDynamicSharedMemorySize, (int)smem1);
    cudaFuncSetAttribute(k2_msg, cudaFuncAttributeMaxDynamicSharedMemorySize, (int)S_K2TOT);
    cudaFuncSetAttribute(k3_ff,  cudaFuncAttributeMaxDynamicSharedMemorySize, (int)smem3);

    dim3 grid1(NRES / 64, 3);
    k1_pre<<<grid1, 256, smem1>>>(node_h, seq_emb, mW1);

    const int ngroups = NRES * NK / 192;   // 2048
    k2_msg<<<nsm, 256, S_K2TOT>>>(edge_h, edge_idx, ar_mask,
                                  mW1, mb1, mW2, mb2, ngroups);

    k3_ff<<<NRES / 32, 256, smem3>>>(node_h, mW3, mb3, fW1, fb1, fW2, fb2,
                                     g1, b1, g2, b2, out);
}

// round 5
// speedup vs baseline: 1.2810x; 1.0516x over previous
#include <cuda_runtime.h>
#include <cuda_bf16.h>
#include <math.h>
#include <stdint.h>

#define NRES 8192
#define NK   48
#define NH   128

__device__ float g_Pi[NRES * NH];
__device__ float g_Pj[NRES * NH];
__device__ float g_Ps[NRES * NH];
__device__ float g_S [NRES * NH];

__device__ __forceinline__ float gelu_exact(float x) {
    return 0.5f * x * (1.0f + erff(x * 0.7071067811865475f));
}
__device__ __forceinline__ uint32_t smem_u32(const void* p) {
    uint32_t a;
    asm("{ .reg .u64 t; cvta.to.shared.u64 t, %1; cvt.u32.u64 %0, t; }" : "=r"(a) : "l"(p));
    return a;
}
__device__ __forceinline__ uint32_t pack_bf(__nv_bfloat16 a, __nv_bfloat16 b) {
    return (uint32_t)__bfloat16_as_ushort(a) | ((uint32_t)__bfloat16_as_ushort(b) << 16);
}
__device__ __forceinline__ void split_bf(float x, __nv_bfloat16& h, __nv_bfloat16& l) {
    h = __float2bfloat16(x);
    l = __float2bfloat16(x - __bfloat162float(h));
}
__device__ __forceinline__ void ldm_x4(uint32_t& r0, uint32_t& r1, uint32_t& r2, uint32_t& r3, uint32_t a) {
    asm volatile("ldmatrix.sync.aligned.m8n8.x4.shared.b16 {%0,%1,%2,%3}, [%4];"
                 : "=r"(r0), "=r"(r1), "=r"(r2), "=r"(r3) : "r"(a));
}
__device__ __forceinline__ void ldm_x2(uint32_t& r0, uint32_t& r1, uint32_t a) {
    asm volatile("ldmatrix.sync.aligned.m8n8.x2.shared.b16 {%0,%1}, [%2];"
                 : "=r"(r0), "=r"(r1) : "r"(a));
}
__device__ __forceinline__ void mma_bf16(float* c, uint32_t a0, uint32_t a1, uint32_t a2, uint32_t a3,
                                         uint32_t b0, uint32_t b1) {
    asm volatile("mma.sync.aligned.m16n8k16.row.col.f32.bf16.bf16.f32 "
                 "{%0,%1,%2,%3}, {%4,%5,%6,%7}, {%8,%9}, {%0,%1,%2,%3};"
                 : "+f"(c[0]), "+f"(c[1]), "+f"(c[2]), "+f"(c[3])
                 : "r"(a0), "r"(a1), "r"(a2), "r"(a3), "r"(b0), "r"(b1));
}

// ---------------------------------------------------------------------------
// Kernel 1: Pi/Pj/Ps projections (fp32, bank-conflict-free column mapping)
// ---------------------------------------------------------------------------
__global__ __launch_bounds__(256) void k1_pre(const float* __restrict__ node_h,
                                              const float* __restrict__ seq_emb,
                                              const float* __restrict__ mW1) {
    extern __shared__ float sm1[];
    float* Wsh = sm1;
    float* Ash = sm1 + 16384;
    const int tid   = threadIdx.x;
    const int which = blockIdx.y;
    const float* A    = (which == 2) ? seq_emb : node_h;
    const float* Wsrc = mW1 + (size_t)(which == 0 ? 0 : (which == 1 ? 128 : 384)) * NH;
    float* out = (which == 0) ? g_Pi : (which == 1 ? g_Pj : g_Ps);

    for (int i = tid; i < 4096; i += 256) ((float4*)Wsh)[i] = ((const float4*)Wsrc)[i];
    const int m0 = blockIdx.x * 64;
    for (int i = tid; i < 2048; i += 256) {
        int r = i >> 5, c4 = i & 31;
        *(float4*)&Ash[r * 132 + c4 * 4] = ((const float4*)(A + (size_t)(m0 + r) * NH))[c4];
    }
    __syncthreads();
    const int tc = tid & 15, tr = tid >> 4;
    float acc[4][8];
#pragma unroll
    for (int i = 0; i < 4; i++)
#pragma unroll
        for (int j = 0; j < 8; j++) acc[i][j] = 0.f;
#pragma unroll 4
    for (int kk = 0; kk < 128; kk++) {
        float4 b0 = *(const float4*)&Wsh[kk * 128 + tc * 4];        // banks 4tc..: conflict-free
        float4 b1 = *(const float4*)&Wsh[kk * 128 + 64 + tc * 4];
#pragma unroll
        for (int i = 0; i < 4; i++) {
            float a = Ash[(tr * 4 + i) * 132 + kk];
            acc[i][0] = fmaf(a, b0.x, acc[i][0]); acc[i][1] = fmaf(a, b0.y, acc[i][1]);
            acc[i][2] = fmaf(a, b0.z, acc[i][2]); acc[i][3] = fmaf(a, b0.w, acc[i][3]);
            acc[i][4] = fmaf(a, b1.x, acc[i][4]); acc[i][5] = fmaf(a, b1.y, acc[i][5]);
            acc[i][6] = fmaf(a, b1.z, acc[i][6]); acc[i][7] = fmaf(a, b1.w, acc[i][7]);
        }
    }
#pragma unroll
    for (int i = 0; i < 4; i++) {
        size_t r = (size_t)(m0 + tr * 4 + i) * NH;
        *(float4*)&out[r + tc * 4]      = make_float4(acc[i][0], acc[i][1], acc[i][2], acc[i][3]);
        *(float4*)&out[r + 64 + tc * 4] = make_float4(acc[i][4], acc[i][5], acc[i][6], acc[i][7]);
    }
}

// ---------------------------------------------------------------------------
// Kernel 2: per-edge MLP via mma.sync bf16 3-pass. 512 threads, 16 warps
// (4M x 4N), tile M=128 x N=128 x K=128. Group = 384 edges (8 residues).
// Acc-init gathers Pi/Pj/Ps directly; epilogue-2 atomically reduces to SSUM.
// ---------------------------------------------------------------------------
#define LDB 272u
#define S_BT1H 0u
#define S_BT1L 34816u
#define S_BT2H 69632u
#define S_BT2L 104448u
#define S_AH   139264u
#define S_AL   174080u
#define S_SSUM 208896u   // 8*128 fp32
#define S_IDX  212992u   // 128 int
#define S_AM   213504u   // 128 fp32
#define S_MB   214016u   // 256 fp32 (mb1|mb2)
#define S_K2TOT 215040u

__global__ __launch_bounds__(512) void k2_msg(const float* __restrict__ edge_h,
                                              const int*   __restrict__ edge_idx,
                                              const float* __restrict__ ar_mask,
                                              const float* __restrict__ mW1,
                                              const float* __restrict__ mb1,
                                              const float* __restrict__ mW2,
                                              const float* __restrict__ mb2,
                                              int ngroups) {
    extern __shared__ char sm[];
    const int tid  = threadIdx.x;
    const int w    = tid >> 5, lane = tid & 31;
    const int gid  = lane >> 2, t4 = lane & 3;
    const int wm   = w >> 2, wn = w & 3;          // 4 x 4 warp grid
    const int m_base = wm * 32, n_base = wn * 32;
    const uint32_t sb = smem_u32(sm);

    float* SSUM = (float*)(sm + S_SSUM);
    int*   IDX  = (int*)(sm + S_IDX);
    float* AM   = (float*)(sm + S_AM);
    float* MB   = (float*)(sm + S_MB);

    if (tid < 128) MB[tid] = mb1[tid];
    else if (tid < 256) MB[tid] = mb2[tid - 128];
    for (int idx = tid; idx < 16384; idx += 512) {
        const int n = idx >> 7, k = idx & 127;
        float w1 = mW1[(size_t)(256 + k) * NH + n];
        float w2 = mW2[(size_t)k * NH + n];
        __nv_bfloat16 h1, l1, h2, l2;
        split_bf(w1, h1, l1); split_bf(w2, h2, l2);
        const uint32_t o = (uint32_t)n * LDB + (uint32_t)k * 2u;
        *(unsigned short*)(sm + S_BT1H + o) = __bfloat16_as_ushort(h1);
        *(unsigned short*)(sm + S_BT1L + o) = __bfloat16_as_ushort(l1);
        *(unsigned short*)(sm + S_BT2H + o) = __bfloat16_as_ushort(h2);
        *(unsigned short*)(sm + S_BT2L + o) = __bfloat16_as_ushort(l2);
    }

    // lane-fixed ldmatrix addresses
    const uint32_t a_row  = (uint32_t)(m_base + (lane & 15));
    const uint32_t a_koff = (uint32_t)((lane >> 4) * 16);
    const uint32_t aH0 = sb + S_AH + a_row * LDB + a_koff;
    const uint32_t aL0 = sb + S_AL + a_row * LDB + a_koff;
    const uint32_t b_row  = (uint32_t)(lane & 7);
    const uint32_t b_koff = (uint32_t)(((lane >> 3) & 1) * 16);
    uint32_t bBase[4];
#pragma unroll
    for (int j = 0; j < 4; j++)
        bBase[j] = (uint32_t)(n_base + j * 8 + b_row) * LDB + b_koff;

    for (int g = blockIdx.x; g < ngroups; g += gridDim.x) {
        __syncthreads();
        for (int i = tid; i < 1024; i += 512) SSUM[i] = 0.f;

        for (int t = 0; t < 3; t++) {
            const int row0 = g * 384 + t * 128;
            __syncthreads();                       // prev tile fully consumed
            if (tid < 128) {
                IDX[tid] = edge_idx[row0 + tid];
                AM[tid]  = ar_mask[row0 + tid];
            }
            // build E -> AH/AL (bf16 hi/lo)
            {
                const int r = tid >> 2, q = tid & 3;
                const float4* E4 = (const float4*)(edge_h + (size_t)(row0 + r) * NH);
#pragma unroll
                for (int c8 = 0; c8 < 8; c8++) {
                    const int c4 = q * 8 + c8;
                    float4 e = E4[c4];
                    __nv_bfloat16 h0, l0, h1, l1, h2, l2, h3, l3;
                    split_bf(e.x, h0, l0); split_bf(e.y, h1, l1);
                    split_bf(e.z, h2, l2); split_bf(e.w, h3, l3);
                    const uint32_t o = (uint32_t)r * LDB + (uint32_t)c4 * 8u;
                    *(uint2*)(sm + S_AH + o) = make_uint2(pack_bf(h0, h1), pack_bf(h2, h3));
                    *(uint2*)(sm + S_AL + o) = make_uint2(pack_bf(l0, l1), pack_bf(l2, l3));
                }
            }
            __syncthreads();

            float acc[2][4][4];

            // ---- GEMM1 acc init: Pi[res] + Pj[nbr] + am*Ps[nbr] + mb1 (direct gathers) ----
#pragma unroll
            for (int i = 0; i < 2; i++) {
                const int rA = m_base + i * 16 + gid;       // tile-local rows rA, rA+8
                const int resA = (row0 + rA) / NK,       resB = (row0 + rA + 8) / NK;
                const int nbrA = IDX[rA],                nbrB = IDX[rA + 8];
                const float amA = AM[rA],                amB = AM[rA + 8];
                const float* PiA = g_Pi + (size_t)resA * NH;
                const float* PiB = g_Pi + (size_t)resB * NH;
                const float* PjA = g_Pj + (size_t)nbrA * NH;
                const float* PjB = g_Pj + (size_t)nbrB * NH;
                const float* PsA = g_Ps + (size_t)nbrA * NH;
                const float* PsB = g_Ps + (size_t)nbrB * NH;
#pragma unroll
                for (int j = 0; j < 4; j++) {
                    const int n_e = n_base + j * 8 + t4 * 2;
                    float2 piA = *(const float2*)&PiA[n_e], piB = *(const float2*)&PiB[n_e];
                    float2 pjA = *(const float2*)&PjA[n_e], pjB = *(const float2*)&PjB[n_e];
                    float2 psA = *(const float2*)&PsA[n_e], psB = *(const float2*)&PsB[n_e];
                    float2 mb = *(const float2*)&MB[n_e];
                    acc[i][j][0] = piA.x + pjA.x + amA * psA.x + mb.x;
                    acc[i][j][1] = piA.y + pjA.y + amA * psA.y + mb.y;
                    acc[i][j][2] = piB.x + pjB.x + amB * psB.x + mb.x;
                    acc[i][j][3] = piB.y + pjB.y + amB * psB.y + mb.y;
                }
            }
            // ---- GEMM1 mma ----
#pragma unroll
            for (int ks = 0; ks < 8; ks++) {
                const uint32_t ko = (uint32_t)ks * 32u;
                uint32_t ah[2][4], al[2][4], bh[4][2], bl[4][2];
#pragma unroll
                for (int i = 0; i < 2; i++) {
                    ldm_x4(ah[i][0], ah[i][1], ah[i][2], ah[i][3], aH0 + (uint32_t)i * 16u * LDB + ko);
                    ldm_x4(al[i][0], al[i][1], al[i][2], al[i][3], aL0 + (uint32_t)i * 16u * LDB + ko);
                }
#pragma unroll
                for (int j = 0; j < 4; j++) {
                    ldm_x2(bh[j][0], bh[j][1], sb + S_BT1H + bBase[j] + ko);
                    ldm_x2(bl[j][0], bl[j][1], sb + S_BT1L + bBase[j] + ko);
                }
#pragma unroll
                for (int i = 0; i < 2; i++)
#pragma unroll
                    for (int j = 0; j < 4; j++) {
                        mma_bf16(acc[i][j], ah[i][0], ah[i][1], ah[i][2], ah[i][3], bh[j][0], bh[j][1]);
                        mma_bf16(acc[i][j], al[i][0], al[i][1], al[i][2], al[i][3], bh[j][0], bh[j][1]);
                        mma_bf16(acc[i][j], ah[i][0], ah[i][1], ah[i][2], ah[i][3], bl[j][0], bl[j][1]);
                    }
            }
            __syncthreads();                       // GEMM1 reads of AH/AL done

            // ---- epilogue 1: X1 = gelu(acc) -> AH/AL ----
#pragma unroll
            for (int i = 0; i < 2; i++) {
                const int m_e = m_base + i * 16 + gid;
#pragma unroll
                for (int j = 0; j < 4; j++) {
                    const int n_e = n_base + j * 8 + t4 * 2;
                    float v0 = gelu_exact(acc[i][j][0]), v1 = gelu_exact(acc[i][j][1]);
                    float v2 = gelu_exact(acc[i][j][2]), v3 = gelu_exact(acc[i][j][3]);
                    __nv_bfloat16 h0, l0, h1, l1, h2, l2, h3, l3;
                    split_bf(v0, h0, l0); split_bf(v1, h1, l1);
                    split_bf(v2, h2, l2); split_bf(v3, h3, l3);
                    const uint32_t o0 = (uint32_t)m_e * LDB + (uint32_t)n_e * 2u;
                    const uint32_t o1 = o0 + 8u * LDB;
                    *(uint32_t*)(sm + S_AH + o0) = pack_bf(h0, h1);
                    *(uint32_t*)(sm + S_AL + o0) = pack_bf(l0, l1);
                    *(uint32_t*)(sm + S_AH + o1) = pack_bf(h2, h3);
                    *(uint32_t*)(sm + S_AL + o1) = pack_bf(l2, l3);
                }
            }
            __syncthreads();

            // ---- GEMM2: acc = mb2 + X1 @ W2 ----
#pragma unroll
            for (int i = 0; i < 2; i++)
#pragma unroll
                for (int j = 0; j < 4; j++) {
                    float2 mb = *(const float2*)&MB[128 + n_base + j * 8 + t4 * 2];
                    acc[i][j][0] = mb.x; acc[i][j][1] = mb.y;
                    acc[i][j][2] = mb.x; acc[i][j][3] = mb.y;
                }
#pragma unroll
            for (int ks = 0; ks < 8; ks++) {
                const uint32_t ko = (uint32_t)ks * 32u;
                uint32_t ah[2][4], al[2][4], bh[4][2], bl[4][2];
#pragma unroll
                for (int i = 0; i < 2; i++) {
                    ldm_x4(ah[i][0], ah[i][1], ah[i][2], ah[i][3], aH0 + (uint32_t)i * 16u * LDB + ko);
                    ldm_x4(al[i][0], al[i][1], al[i][2], al[i][3], aL0 + (uint32_t)i * 16u * LDB + ko);
                }
#pragma unroll
                for (int j = 0; j < 4; j++) {
                    ldm_x2(bh[j][0], bh[j][1], sb + S_BT2H + bBase[j] + ko);
                    ldm_x2(bl[j][0], bl[j][1], sb + S_BT2L + bBase[j] + ko);
                }
#pragma unroll
                for (int i = 0; i < 2; i++)
#pragma unroll
                    for (int j = 0; j < 4; j++) {
                        mma_bf16(acc[i][j], ah[i][0], ah[i][1], ah[i][2], ah[i][3], bh[j][0], bh[j][1]);
                        mma_bf16(acc[i][j], al[i][0], al[i][1], al[i][2], al[i][3], bh[j][0], bh[j][1]);
                        mma_bf16(acc[i][j], ah[i][0], ah[i][1], ah[i][2], ah[i][3], bl[j][0], bl[j][1]);
                    }
            }

            // ---- epilogue 2: gelu -> atomic segmented sum into SSUM ----
#pragma unroll
            for (int i = 0; i < 2; i++) {
                const int rA = m_base + i * 16 + gid;
                const int rlA = (t * 128 + rA) / NK;        // group-local residue 0..7
                const int rlB = (t * 128 + rA + 8) / NK;
#pragma unroll
                for (int j = 0; j < 4; j++) {
                    const int n_e = n_base + j * 8 + t4 * 2;
                    atomicAdd(&SSUM[rlA * 128 + n_e],     gelu_exact(acc[i][j][0]));
                    atomicAdd(&SSUM[rlA * 128 + n_e + 1], gelu_exact(acc[i][j][1]));
                    atomicAdd(&SSUM[rlB * 128 + n_e],     gelu_exact(acc[i][j][2]));
                    atomicAdd(&SSUM[rlB * 128 + n_e + 1], gelu_exact(acc[i][j][3]));
                }
            }
        }
        __syncthreads();
        for (int i = tid; i < 1024; i += 512)
            g_S[(size_t)g * 1024 + i] = SSUM[i];
    }
}

// ---------------------------------------------------------------------------
// Kernel 3: agg = S@W3 + 48*mb3; LN1; FFN; LN2 (bank-conflict-free columns)
// ---------------------------------------------------------------------------
__global__ __launch_bounds__(256) void k3_ff(const float* __restrict__ node_h,
                                             const float* __restrict__ mW3,
                                             const float* __restrict__ mb3,
                                             const float* __restrict__ fW1,
                                             const float* __restrict__ fb1,
                                             const float* __restrict__ fW2,
                                             const float* __restrict__ fb2,
                                             const float* __restrict__ g1,
                                             const float* __restrict__ b1,
                                             const float* __restrict__ g2,
                                             const float* __restrict__ b2,
                                             float* __restrict__ out) {
    extern __shared__ float sm3[];
    float* H1sh = sm3;                        // 32*132
    float* Tsh  = sm3 + 32 * 132;             // 32*516
    float* Wsh  = sm3 + 32 * 132 + 32 * 516;  // 128*128

    const int tid = threadIdx.x;
    const int wid = tid >> 5, lane = tid & 31;
    const int m0  = blockIdx.x * 32;
    const int tc = tid & 15, tr = tid >> 4;

    for (int i = tid; i < 4096; i += 256) ((float4*)Wsh)[i] = ((const float4*)mW3)[i];
    for (int i = tid; i < 1024; i += 256) {
        int r = i >> 5, c4 = i & 31;
        *(float4*)&Tsh[r * 132 + c4 * 4] = ((const float4*)(g_S + (size_t)(m0 + r) * NH))[c4];
    }
    __syncthreads();

    {
        float acc[2][8];
#pragma unroll
        for (int i = 0; i < 2; i++)
#pragma unroll
            for (int j = 0; j < 8; j++)
                acc[i][j] = 48.f * mb3[(j < 4 ? tc * 4 + j : 64 + tc * 4 + j - 4)];
#pragma unroll 4
        for (int kk = 0; kk < 128; kk++) {
            float4 b0 = *(const float4*)&Wsh[kk * 128 + tc * 4];
            float4 b1v = *(const float4*)&Wsh[kk * 128 + 64 + tc * 4];
#pragma unroll
            for (int i = 0; i < 2; i++) {
                float a = Tsh[(tr * 2 + i) * 132 + kk];
                acc[i][0] = fmaf(a, b0.x, acc[i][0]); acc[i][1] = fmaf(a, b0.y, acc[i][1]);
                acc[i][2] = fmaf(a, b0.z, acc[i][2]); acc[i][3] = fmaf(a, b0.w, acc[i][3]);
                acc[i][4] = fmaf(a, b1v.x, acc[i][4]); acc[i][5] = fmaf(a, b1v.y, acc[i][5]);
                acc[i][6] = fmaf(a, b1v.z, acc[i][6]); acc[i][7] = fmaf(a, b1v.w, acc[i][7]);
            }
        }
#pragma unroll
        for (int i = 0; i < 2; i++) {
            const float* nrow = node_h + (size_t)(m0 + tr * 2 + i) * NH;
            float4 n0 = *(const float4*)&nrow[tc * 4];
            float4 n1 = *(const float4*)&nrow[64 + tc * 4];
            float* hrow = &H1sh[(tr * 2 + i) * 132];
            hrow[tc * 4 + 0] = acc[i][0] + n0.x; hrow[tc * 4 + 1] = acc[i][1] + n0.y;
            hrow[tc * 4 + 2] = acc[i][2] + n0.z; hrow[tc * 4 + 3] = acc[i][3] + n0.w;
            hrow[64 + tc * 4 + 0] = acc[i][4] + n1.x; hrow[64 + tc * 4 + 1] = acc[i][5] + n1.y;
            hrow[64 + tc * 4 + 2] = acc[i][6] + n1.z; hrow[64 + tc * 4 + 3] = acc[i][7] + n1.w;
        }
    }
    __syncthreads();

    for (int r = wid; r < 32; r += 8) {
        const int c0 = lane * 4;
        float v0 = H1sh[r * 132 + c0], v1 = H1sh[r * 132 + c0 + 1];
        float v2 = H1sh[r * 132 + c0 + 2], v3 = H1sh[r * 132 + c0 + 3];
        float s = v0 + v1 + v2 + v3;
#pragma unroll
        for (int o = 16; o; o >>= 1) s += __shfl_xor_sync(0xffffffffu, s, o);
        float mu = s * (1.f / 128.f);
        float d0 = v0 - mu, d1 = v1 - mu, d2 = v2 - mu, d3 = v3 - mu;
        float q = d0 * d0 + d1 * d1 + d2 * d2 + d3 * d3;
#pragma unroll
        for (int o = 16; o; o >>= 1) q += __shfl_xor_sync(0xffffffffu, q, o);
        float rs = rsqrtf(q * (1.f / 128.f) + 1e-5f);
        H1sh[r * 132 + c0]     = d0 * rs * g1[c0]     + b1[c0];
        H1sh[r * 132 + c0 + 1] = d1 * rs * g1[c0 + 1] + b1[c0 + 1];
        H1sh[r * 132 + c0 + 2] = d2 * rs * g1[c0 + 2] + b1[c0 + 2];
        H1sh[r * 132 + c0 + 3] = d3 * rs * g1[c0 + 3] + b1[c0 + 3];
    }

    for (int nc = 0; nc < 4; nc++) {
        __syncthreads();
        for (int i = tid; i < 4096; i += 256) {
            int k = i >> 5, c4 = i & 31;
            ((float4*)&Wsh[k * 128])[c4] = ((const float4*)&fW1[(size_t)k * 512 + nc * 128])[c4];
        }
        __syncthreads();
        float acc[2][8];
#pragma unroll
        for (int i = 0; i < 2; i++)
#pragma unroll
            for (int j = 0; j < 8; j++)
                acc[i][j] = fb1[nc * 128 + (j < 4 ? tc * 4 + j : 64 + tc * 4 + j - 4)];
#pragma unroll 4
        for (int kk = 0; kk < 128; kk++) {
            float4 b0 = *(const float4*)&Wsh[kk * 128 + tc * 4];
            float4 b1v = *(const float4*)&Wsh[kk * 128 + 64 + tc * 4];
#pragma unroll
            for (int i = 0; i < 2; i++) {
                float a = H1sh[(tr * 2 + i) * 132 + kk];
                acc[i][0] = fmaf(a, b0.x, acc[i][0]); acc[i][1] = fmaf(a, b0.y, acc[i][1]);
                acc[i][2] = fmaf(a, b0.z, acc[i][2]); acc[i][3] = fmaf(a, b0.w, acc[i][3]);
                acc[i][4] = fmaf(a, b1v.x, acc[i][4]); acc[i][5] = fmaf(a, b1v.y, acc[i][5]);
                acc[i][6] = fmaf(a, b1v.z, acc[i][6]); acc[i][7] = fmaf(a, b1v.w, acc[i][7]);
            }
        }
#pragma unroll
        for (int i = 0; i < 2; i++) {
            float* trow = &Tsh[(tr * 2 + i) * 516 + nc * 128];
#pragma unroll
            for (int j = 0; j < 4; j++) trow[tc * 4 + j]      = gelu_exact(acc[i][j]);
#pragma unroll
            for (int j = 0; j < 4; j++) trow[64 + tc * 4 + j] = gelu_exact(acc[i][4 + j]);
        }
    }

    float acc2[2][8];
#pragma unroll
    for (int i = 0; i < 2; i++)
#pragma unroll
        for (int j = 0; j < 8; j++)
            acc2[i][j] = fb2[(j < 4 ? tc * 4 + j : 64 + tc * 4 + j - 4)];
    for (int kc = 0; kc < 4; kc++) {
        __syncthreads();
        for (int i = tid; i < 4096; i += 256) {
            int k = i >> 5, c4 = i & 31;
            ((float4*)&Wsh[k * 128])[c4] = ((const float4*)&fW2[(size_t)(kc * 128 + k) * 128])[c4];
        }
        __syncthreads();
#pragma unroll 4
        for (int kk = 0; kk < 128; kk++) {
            float4 b0 = *(const float4*)&Wsh[kk * 128 + tc * 4];
            float4 b1v = *(const float4*)&Wsh[kk * 128 + 64 + tc * 4];
#pragma unroll
            for (int i = 0; i < 2; i++) {
                float a = Tsh[(tr * 2 + i) * 516 + kc * 128 + kk];
                acc2[i][0] = fmaf(a, b0.x, acc2[i][0]); acc2[i][1] = fmaf(a, b0.y, acc2[i][1]);
                acc2[i][2] = fmaf(a, b0.z, acc2[i][2]); acc2[i][3] = fmaf(a, b0.w, acc2[i][3]);
                acc2[i][4] = fmaf(a, b1v.x, acc2[i][4]); acc2[i][5] = fmaf(a, b1v.y, acc2[i][5]);
                acc2[i][6] = fmaf(a, b1v.z, acc2[i][6]); acc2[i][7] = fmaf(a, b1v.w, acc2[i][7]);
            }
        }
    }

    __syncthreads();
    float* Vsh = Tsh;
#pragma unroll
    for (int i = 0; i < 2; i++) {
        const int r = tr * 2 + i;
#pragma unroll
        for (int j = 0; j < 4; j++) Vsh[r * 132 + tc * 4 + j]      = H1sh[r * 132 + tc * 4 + j] + acc2[i][j];
#pragma unroll
        for (int j = 0; j < 4; j++) Vsh[r * 132 + 64 + tc * 4 + j] = H1sh[r * 132 + 64 + tc * 4 + j] + acc2[i][4 + j];
    }
    __syncthreads();
    for (int r = wid; r < 32; r += 8) {
        const int c0 = lane * 4;
        float v0 = Vsh[r * 132 + c0], v1 = Vsh[r * 132 + c0 + 1];
        float v2 = Vsh[r * 132 + c0 + 2], v3 = Vsh[r * 132 + c0 + 3];
        float s = v0 + v1 + v2 + v3;
#pragma unroll
        for (int o = 16; o; o >>= 1) s += __shfl_xor_sync(0xffffffffu, s, o);
        float mu = s * (1.f / 128.f);
        float d0 = v0 - mu, d1 = v1 - mu, d2 = v2 - mu, d3 = v3 - mu;
        float q = d0 * d0 + d1 * d1 + d2 * d2 + d3 * d3;
#pragma unroll
        for (int o = 16; o; o >>= 1) q += __shfl_xor_sync(0xffffffffu, q, o);
        float rs = rsqrtf(q * (1.f / 128.f) + 1e-5f);
        float4 o4;
        o4.x = d0 * rs * g2[c0]     + b2[c0];
        o4.y = d1 * rs * g2[c0 + 1] + b2[c0 + 1];
        o4.z = d2 * rs * g2[c0 + 2] + b2[c0 + 2];
        o4.w = d3 * rs * g2[c0 + 3] + b2[c0 + 3];
        *(float4*)&out[(size_t)(m0 + r) * NH + c0] = o4;
    }
}

// ---------------------------------------------------------------------------
extern "C" void kernel_launch(void* const* d_in, const int* in_sizes, int n_in,
                              void* d_out, int out_size) {
    const float* node_h   = (const float*)d_in[0];
    const float* edge_h   = (const float*)d_in[1];
    const int*   edge_idx = (const int*)d_in[2];
    const float* seq_emb  = (const float*)d_in[3];
    const float* ar_mask  = (const float*)d_in[4];
    const float* mW1 = (const float*)d_in[5];
    const float* mb1 = (const float*)d_in[6];
    const float* mW2 = (const float*)d_in[7];
    const float* mb2 = (const float*)d_in[8];
    const float* mW3 = (const float*)d_in[9];
    const float* mb3 = (const float*)d_in[10];
    const float* fW1 = (const float*)d_in[11];
    const float* fb1 = (const float*)d_in[12];
    const float* fW2 = (const float*)d_in[13];
    const float* fb2 = (const float*)d_in[14];
    const float* g1  = (const float*)d_in[15];
    const float* b1  = (const float*)d_in[16];
    const float* g2  = (const float*)d_in[17];
    const float* b2  = (const float*)d_in[18];
    float* out = (float*)d_out;

    int dev = 0;
    cudaGetDevice(&dev);
    int nsm = 148;
    cudaDeviceGetAttribute(&nsm, cudaDevAttrMultiProcessorCount, dev);

    const size_t smem1 = (size_t)(16384 + 64 * 132) * sizeof(float);
    const size_t smem3 = (size_t)(32 * 132 + 32 * 516 + 16384) * sizeof(float);

    cudaFuncSetAttribute(k1_pre, cudaFuncAttributeMaxDynamicSharedMemorySize, (int)smem1);
    cudaFuncSetAttribute(k2_msg, cudaFuncAttributeMaxDynamicSharedMemorySize, (int)S_K2TOT);
    cudaFuncSetAttribute(k3_ff,  cudaFuncAttributeMaxDynamicSharedMemorySize, (int)smem3);

    dim3 grid1(NRES / 64, 3);
    k1_pre<<<grid1, 256, smem1>>>(node_h, seq_emb, mW1);

    const int ngroups = NRES / 8;   // 1024 groups of 384 edges
    k2_msg<<<nsm, 512, S_K2TOT>>>(edge_h, edge_idx, ar_mask,
                                  mW1, mb1, mW2, mb2, ngroups);

    k3_ff<<<NRES / 32, 256, smem3>>>(node_h, mW3, mb3, fW1, fb1, fW2, fb2,
                                     g1, b1, g2, b2, out);
}

// round 6
// speedup vs baseline: 1.4422x; 1.1259x over previous
#include <cuda_runtime.h>
#include <cuda_fp16.h>
#include <math.h>
#include <stdint.h>

#define NRES 8192
#define NK   48
#define NH   128

__device__ float g_Pi[NRES * NH];
__device__ float g_Pj[NRES * NH];
__device__ float g_Ps[NRES * NH];
__device__ float g_S [NRES * NH];

__device__ __forceinline__ float gelu_exact(float x) {
    return 0.5f * x * (1.0f + erff(x * 0.7071067811865475f));
}
__device__ __forceinline__ uint32_t smem_u32(const void* p) {
    uint32_t a;
    asm("{ .reg .u64 t; cvta.to.shared.u64 t, %1; cvt.u32.u64 %0, t; }" : "=r"(a) : "l"(p));
    return a;
}
__device__ __forceinline__ uint32_t pack_h2(float a, float b) {
    __half2 h = __floats2half2_rn(a, b);
    return *reinterpret_cast<uint32_t*>(&h);
}
__device__ __forceinline__ void ldm_x4(uint32_t& r0, uint32_t& r1, uint32_t& r2, uint32_t& r3, uint32_t a) {
    asm volatile("ldmatrix.sync.aligned.m8n8.x4.shared.b16 {%0,%1,%2,%3}, [%4];"
                 : "=r"(r0), "=r"(r1), "=r"(r2), "=r"(r3) : "r"(a));
}
__device__ __forceinline__ void ldm_x2(uint32_t& r0, uint32_t& r1, uint32_t a) {
    asm volatile("ldmatrix.sync.aligned.m8n8.x2.shared.b16 {%0,%1}, [%2];"
                 : "=r"(r0), "=r"(r1) : "r"(a));
}
__device__ __forceinline__ void mma_f16(float* c, uint32_t a0, uint32_t a1, uint32_t a2, uint32_t a3,
                                        uint32_t b0, uint32_t b1) {
    asm volatile("mma.sync.aligned.m16n8k16.row.col.f32.f16.f16.f32 "
                 "{%0,%1,%2,%3}, {%4,%5,%6,%7}, {%8,%9}, {%0,%1,%2,%3};"
                 : "+f"(c[0]), "+f"(c[1]), "+f"(c[2]), "+f"(c[3])
                 : "r"(a0), "r"(a1), "r"(a2), "r"(a3), "r"(b0), "r"(b1));
}

// ---------------------------------------------------------------------------
// Kernel 1: Pi/Pj/Ps projections (fp32, conflict-free columns) — round-5 proven
// ---------------------------------------------------------------------------
__global__ __launch_bounds__(256) void k1_pre(const float* __restrict__ node_h,
                                              const float* __restrict__ seq_emb,
                                              const float* __restrict__ mW1) {
    extern __shared__ float sm1[];
    float* Wsh = sm1;
    float* Ash = sm1 + 16384;
    const int tid   = threadIdx.x;
    const int which = blockIdx.y;
    const float* A    = (which == 2) ? seq_emb : node_h;
    const float* Wsrc = mW1 + (size_t)(which == 0 ? 0 : (which == 1 ? 128 : 384)) * NH;
    float* out = (which == 0) ? g_Pi : (which == 1 ? g_Pj : g_Ps);

    for (int i = tid; i < 4096; i += 256) ((float4*)Wsh)[i] = ((const float4*)Wsrc)[i];
    const int m0 = blockIdx.x * 64;
    for (int i = tid; i < 2048; i += 256) {
        int r = i >> 5, c4 = i & 31;
        *(float4*)&Ash[r * 132 + c4 * 4] = ((const float4*)(A + (size_t)(m0 + r) * NH))[c4];
    }
    __syncthreads();
    const int tc = tid & 15, tr = tid >> 4;
    float acc[4][8];
#pragma unroll
    for (int i = 0; i < 4; i++)
#pragma unroll
        for (int j = 0; j < 8; j++) acc[i][j] = 0.f;
#pragma unroll 4
    for (int kk = 0; kk < 128; kk++) {
        float4 b0 = *(const float4*)&Wsh[kk * 128 + tc * 4];
        float4 b1 = *(const float4*)&Wsh[kk * 128 + 64 + tc * 4];
#pragma unroll
        for (int i = 0; i < 4; i++) {
            float a = Ash[(tr * 4 + i) * 132 + kk];
            acc[i][0] = fmaf(a, b0.x, acc[i][0]); acc[i][1] = fmaf(a, b0.y, acc[i][1]);
            acc[i][2] = fmaf(a, b0.z, acc[i][2]); acc[i][3] = fmaf(a, b0.w, acc[i][3]);
            acc[i][4] = fmaf(a, b1.x, acc[i][4]); acc[i][5] = fmaf(a, b1.y, acc[i][5]);
            acc[i][6] = fmaf(a, b1.z, acc[i][6]); acc[i][7] = fmaf(a, b1.w, acc[i][7]);
        }
    }
#pragma unroll
    for (int i = 0; i < 4; i++) {
        size_t r = (size_t)(m0 + tr * 4 + i) * NH;
        *(float4*)&out[r + tc * 4]      = make_float4(acc[i][0], acc[i][1], acc[i][2], acc[i][3]);
        *(float4*)&out[r + 64 + tc * 4] = make_float4(acc[i][4], acc[i][5], acc[i][6], acc[i][7]);
    }
}

// ---------------------------------------------------------------------------
// Kernel 2: per-edge MLP. fp16 A (single) x fp16 W (hi+lo split), 2 mma passes
// per GEMM (W exact to 2^-22). cp.async pipeline: 96/128 rows of next E tile
// + next IDX/AM prefetched during current tile's MMA phase.
// 512 threads, 16 warps (4M x 4N), tile M=128 N=128 K=128.
// ---------------------------------------------------------------------------
#define LDB 272u
#define S_W1H 0u
#define S_W1L 34816u
#define S_W2H 69632u
#define S_W2L 104448u
#define S_A   139264u    // 128 x LDB fp16 (E, then X1)
#define S_STG 174080u    // 96 x 128 fp32 staging (49152 B)
#define S_SSUM 223232u   // 8*128 fp32
#define S_IDX 227328u    // [2][128] int
#define S_AM  228352u    // [2][128] float
#define S_MB  229376u    // 256 fp32 (mb1|mb2)
#define S_K2TOT 230400u

__device__ __forceinline__ void do_prefetch(uint32_t sb, const float* edge_h,
                                            const int* edge_idx, const float* ar_mask,
                                            int row0, int pp, int tid) {
    const char* src = (const char*)(edge_h + (size_t)row0 * NH);
#pragma unroll
    for (int k = 0; k < 6; k++) {
        uint32_t off = (uint32_t)(tid + k * 512) * 16u;
        asm volatile("cp.async.cg.shared.global [%0], [%1], 16;"
                     :: "r"(sb + S_STG + off), "l"(src + off));
    }
    if (tid < 128)
        asm volatile("cp.async.ca.shared.global [%0], [%1], 4;"
                     :: "r"(sb + S_IDX + (uint32_t)pp * 512u + (uint32_t)tid * 4u),
                        "l"(edge_idx + row0 + tid));
    else if (tid < 256)
        asm volatile("cp.async.ca.shared.global [%0], [%1], 4;"
                     :: "r"(sb + S_AM + (uint32_t)pp * 512u + (uint32_t)(tid - 128) * 4u),
                        "l"(ar_mask + row0 + (tid - 128)));
    asm volatile("cp.async.commit_group;" ::: "memory");
}

__global__ __launch_bounds__(512) void k2_msg(const float* __restrict__ edge_h,
                                              const int*   __restrict__ edge_idx,
                                              const float* __restrict__ ar_mask,
                                              const float* __restrict__ mW1,
                                              const float* __restrict__ mb1,
                                              const float* __restrict__ mW2,
                                              const float* __restrict__ mb2,
                                              int ngroups) {
    extern __shared__ char sm[];
    const int tid  = threadIdx.x;
    const int w    = tid >> 5, lane = tid & 31;
    const int gid  = lane >> 2, t4 = lane & 3;
    const int wm   = w >> 2, wn = w & 3;
    const int m_base = wm * 32, n_base = wn * 32;
    const uint32_t sb = smem_u32(sm);

    float* SSUM = (float*)(sm + S_SSUM);
    float* MB   = (float*)(sm + S_MB);
    float* STG  = (float*)(sm + S_STG);

    if (tid < 128) MB[tid] = mb1[tid];
    else if (tid < 256) MB[tid] = mb2[tid - 128];

    // stage W1c^T / W2^T as fp16 hi/lo (weight exact to 2^-22 across 2 passes)
    for (int idx = tid; idx < 16384; idx += 512) {
        const int n = idx >> 7, k = idx & 127;
        float w1 = mW1[(size_t)(256 + k) * NH + n];
        float w2 = mW2[(size_t)k * NH + n];
        __half h1 = __float2half_rn(w1), l1 = __float2half_rn(w1 - __half2float(h1));
        __half h2 = __float2half_rn(w2), l2 = __float2half_rn(w2 - __half2float(h2));
        const uint32_t o = (uint32_t)n * LDB + (uint32_t)k * 2u;
        *(__half*)(sm + S_W1H + o) = h1;
        *(__half*)(sm + S_W1L + o) = l1;
        *(__half*)(sm + S_W2H + o) = h2;
        *(__half*)(sm + S_W2L + o) = l2;
    }

    // lane-fixed ldmatrix addresses
    const uint32_t aBase = sb + S_A + (uint32_t)(m_base + (lane & 15)) * LDB
                         + (uint32_t)((lane >> 4) * 16);
    const uint32_t b_off = (uint32_t)(lane & 7) * LDB + (uint32_t)(((lane >> 3) & 1) * 16);
    uint32_t bOf[4];
#pragma unroll
    for (int j = 0; j < 4; j++)
        bOf[j] = (uint32_t)(n_base + j * 8) * LDB + b_off;

    int pp = 0;
    if ((int)blockIdx.x < ngroups)
        do_prefetch(sb, edge_h, edge_idx, ar_mask, blockIdx.x * 384, 0, tid);

    for (int g = blockIdx.x; g < ngroups; g += gridDim.x) {
        for (int t = 0; t < 3; t++) {
            const int row0 = g * 384 + t * 128;
            asm volatile("cp.async.wait_group 0;" ::: "memory");
            __syncthreads();   // staged data visible; prev GEMM2 reads of A done; prev g_S store done
            if (t == 0)
                for (int i = tid; i < 1024; i += 512) SSUM[i] = 0.f;

            // convert staged rows 0-95 (LDS) -> A fp16
#pragma unroll
            for (int k2i = 0; k2i < 6; k2i++) {
                const int i = tid + k2i * 512;
                const int r = i >> 5, c4 = i & 31;
                float4 e = *(const float4*)((const char*)STG + (size_t)i * 16);
                const uint32_t o = (uint32_t)r * LDB + (uint32_t)c4 * 8u;
                *(uint2*)(sm + S_A + o) = make_uint2(pack_h2(e.x, e.y), pack_h2(e.z, e.w));
            }
            // direct rows 96-127 (LDG)
#pragma unroll
            for (int k2i = 0; k2i < 2; k2i++) {
                const int i = tid + k2i * 512;
                const int r = 96 + (i >> 5), c4 = i & 31;
                float4 e = ((const float4*)(edge_h + (size_t)(row0 + r) * NH))[c4];
                const uint32_t o = (uint32_t)r * LDB + (uint32_t)c4 * 8u;
                *(uint2*)(sm + S_A + o) = make_uint2(pack_h2(e.x, e.y), pack_h2(e.z, e.w));
            }
            __syncthreads();   // A ready; staging free

            // prefetch next tile while we compute this one
            {
                int nt = t + 1, ng = g;
                if (nt == 3) { nt = 0; ng = g + gridDim.x; }
                if (ng < ngroups)
                    do_prefetch(sb, edge_h, edge_idx, ar_mask, ng * 384 + nt * 128, pp ^ 1, tid);
            }

            const int*   IDXc = (const int*)(sm + S_IDX) + pp * 128;
            const float* AMc  = (const float*)(sm + S_AM) + pp * 128;

            float acc[2][4][4];

            // ---- GEMM1 acc init: Pi + Pj + am*Ps + mb1 (fp32 gathers, exact) ----
#pragma unroll
            for (int i = 0; i < 2; i++) {
                const int rA = m_base + i * 16 + gid;
                const int resA = (row0 + rA) / NK,  resB = (row0 + rA + 8) / NK;
                const int nbrA = IDXc[rA],          nbrB = IDXc[rA + 8];
                const float amA = AMc[rA],          amB = AMc[rA + 8];
                const float* PiA = g_Pi + (size_t)resA * NH;
                const float* PiB = g_Pi + (size_t)resB * NH;
                const float* PjA = g_Pj + (size_t)nbrA * NH;
                const float* PjB = g_Pj + (size_t)nbrB * NH;
                const float* PsA = g_Ps + (size_t)nbrA * NH;
                const float* PsB = g_Ps + (size_t)nbrB * NH;
#pragma unroll
                for (int j = 0; j < 4; j++) {
                    const int n_e = n_base + j * 8 + t4 * 2;
                    float2 piA = *(const float2*)&PiA[n_e], piB = *(const float2*)&PiB[n_e];
                    float2 pjA = *(const float2*)&PjA[n_e], pjB = *(const float2*)&PjB[n_e];
                    float2 psA = *(const float2*)&PsA[n_e], psB = *(const float2*)&PsB[n_e];
                    float2 mb = *(const float2*)&MB[n_e];
                    acc[i][j][0] = piA.x + pjA.x + amA * psA.x + mb.x;
                    acc[i][j][1] = piA.y + pjA.y + amA * psA.y + mb.y;
                    acc[i][j][2] = piB.x + pjB.x + amB * psB.x + mb.x;
                    acc[i][j][3] = piB.y + pjB.y + amB * psB.y + mb.y;
                }
            }
            // ---- GEMM1: acc += E @ (W1h + W1l) ----
#pragma unroll
            for (int ks = 0; ks < 8; ks++) {
                const uint32_t ko = (uint32_t)ks * 32u;
                uint32_t a[2][4], bh[4][2], bl[4][2];
                ldm_x4(a[0][0], a[0][1], a[0][2], a[0][3], aBase + ko);
                ldm_x4(a[1][0], a[1][1], a[1][2], a[1][3], aBase + 16u * LDB + ko);
#pragma unroll
                for (int j = 0; j < 4; j++) {
                    ldm_x2(bh[j][0], bh[j][1], sb + S_W1H + bOf[j] + ko);
                    ldm_x2(bl[j][0], bl[j][1], sb + S_W1L + bOf[j] + ko);
                }
#pragma unroll
                for (int i = 0; i < 2; i++)
#pragma unroll
                    for (int j = 0; j < 4; j++) {
                        mma_f16(acc[i][j], a[i][0], a[i][1], a[i][2], a[i][3], bh[j][0], bh[j][1]);
                        mma_f16(acc[i][j], a[i][0], a[i][1], a[i][2], a[i][3], bl[j][0], bl[j][1]);
                    }
            }
            __syncthreads();   // GEMM1 reads of A done

            // ---- epilogue 1: X1 = gelu(acc) -> A (fp16 single) ----
#pragma unroll
            for (int i = 0; i < 2; i++) {
                const int m_e = m_base + i * 16 + gid;
#pragma unroll
                for (int j = 0; j < 4; j++) {
                    const int n_e = n_base + j * 8 + t4 * 2;
                    float v0 = gelu_exact(acc[i][j][0]), v1 = gelu_exact(acc[i][j][1]);
                    float v2 = gelu_exact(acc[i][j][2]), v3 = gelu_exact(acc[i][j][3]);
                    const uint32_t o0 = (uint32_t)m_e * LDB + (uint32_t)n_e * 2u;
                    const uint32_t o1 = o0 + 8u * LDB;
                    *(uint32_t*)(sm + S_A + o0) = pack_h2(v0, v1);
                    *(uint32_t*)(sm + S_A + o1) = pack_h2(v2, v3);
                }
            }
            __syncthreads();

            // ---- GEMM2: acc = mb2 + X1 @ (W2h + W2l) ----
#pragma unroll
            for (int i = 0; i < 2; i++)
#pragma unroll
                for (int j = 0; j < 4; j++) {
                    float2 mb = *(const float2*)&MB[128 + n_base + j * 8 + t4 * 2];
                    acc[i][j][0] = mb.x; acc[i][j][1] = mb.y;
                    acc[i][j][2] = mb.x; acc[i][j][3] = mb.y;
                }
#pragma unroll
            for (int ks = 0; ks < 8; ks++) {
                const uint32_t ko = (uint32_t)ks * 32u;
                uint32_t a[2][4], bh[4][2], bl[4][2];
                ldm_x4(a[0][0], a[0][1], a[0][2], a[0][3], aBase + ko);
                ldm_x4(a[1][0], a[1][1], a[1][2], a[1][3], aBase + 16u * LDB + ko);
#pragma unroll
                for (int j = 0; j < 4; j++) {
                    ldm_x2(bh[j][0], bh[j][1], sb + S_W2H + bOf[j] + ko);
                    ldm_x2(bl[j][0], bl[j][1], sb + S_W2L + bOf[j] + ko);
                }
#pragma unroll
                for (int i = 0; i < 2; i++)
#pragma unroll
                    for (int j = 0; j < 4; j++) {
                        mma_f16(acc[i][j], a[i][0], a[i][1], a[i][2], a[i][3], bh[j][0], bh[j][1]);
                        mma_f16(acc[i][j], a[i][0], a[i][1], a[i][2], a[i][3], bl[j][0], bl[j][1]);
                    }
            }

            // ---- epilogue 2: gelu -> atomic segmented sum into SSUM ----
#pragma unroll
            for (int i = 0; i < 2; i++) {
                const int rA = m_base + i * 16 + gid;
                const int rlA = (t * 128 + rA) / NK;
                const int rlB = (t * 128 + rA + 8) / NK;
#pragma unroll
                for (int j = 0; j < 4; j++) {
                    const int n_e = n_base + j * 8 + t4 * 2;
                    atomicAdd(&SSUM[rlA * 128 + n_e],     gelu_exact(acc[i][j][0]));
                    atomicAdd(&SSUM[rlA * 128 + n_e + 1], gelu_exact(acc[i][j][1]));
                    atomicAdd(&SSUM[rlB * 128 + n_e],     gelu_exact(acc[i][j][2]));
                    atomicAdd(&SSUM[rlB * 128 + n_e + 1], gelu_exact(acc[i][j][3]));
                }
            }
            pp ^= 1;
        }
        __syncthreads();
        for (int i = tid; i < 1024; i += 512)
            g_S[(size_t)g * 1024 + i] = SSUM[i];
    }
}

// ---------------------------------------------------------------------------
// Kernel 3: agg = S@W3 + 48*mb3; LN1; FFN; LN2 (round-5 proven)
// ---------------------------------------------------------------------------
__global__ __launch_bounds__(256) void k3_ff(const float* __restrict__ node_h,
                                             const float* __restrict__ mW3,
                                             const float* __restrict__ mb3,
                                             const float* __restrict__ fW1,
                                             const float* __restrict__ fb1,
                                             const float* __restrict__ fW2,
                                             const float* __restrict__ fb2,
                                             const float* __restrict__ g1,
                                             const float* __restrict__ b1,
                                             const float* __restrict__ g2,
                                             const float* __restrict__ b2,
                                             float* __restrict__ out) {
    extern __shared__ float sm3[];
    float* H1sh = sm3;
    float* Tsh  = sm3 + 32 * 132;
    float* Wsh  = sm3 + 32 * 132 + 32 * 516;

    const int tid = threadIdx.x;
    const int wid = tid >> 5, lane = tid & 31;
    const int m0  = blockIdx.x * 32;
    const int tc = tid & 15, tr = tid >> 4;

    for (int i = tid; i < 4096; i += 256) ((float4*)Wsh)[i] = ((const float4*)mW3)[i];
    for (int i = tid; i < 1024; i += 256) {
        int r = i >> 5, c4 = i & 31;
        *(float4*)&Tsh[r * 132 + c4 * 4] = ((const float4*)(g_S + (size_t)(m0 + r) * NH))[c4];
    }
    __syncthreads();

    {
        float acc[2][8];
#pragma unroll
        for (int i = 0; i < 2; i++)
#pragma unroll
            for (int j = 0; j < 8; j++)
                acc[i][j] = 48.f * mb3[(j < 4 ? tc * 4 + j : 64 + tc * 4 + j - 4)];
#pragma unroll 4
        for (int kk = 0; kk < 128; kk++) {
            float4 b0 = *(const float4*)&Wsh[kk * 128 + tc * 4];
            float4 b1v = *(const float4*)&Wsh[kk * 128 + 64 + tc * 4];
#pragma unroll
            for (int i = 0; i < 2; i++) {
                float a = Tsh[(tr * 2 + i) * 132 + kk];
                acc[i][0] = fmaf(a, b0.x, acc[i][0]); acc[i][1] = fmaf(a, b0.y, acc[i][1]);
                acc[i][2] = fmaf(a, b0.z, acc[i][2]); acc[i][3] = fmaf(a, b0.w, acc[i][3]);
                acc[i][4] = fmaf(a, b1v.x, acc[i][4]); acc[i][5] = fmaf(a, b1v.y, acc[i][5]);
                acc[i][6] = fmaf(a, b1v.z, acc[i][6]); acc[i][7] = fmaf(a, b1v.w, acc[i][7]);
            }
        }
#pragma unroll
        for (int i = 0; i < 2; i++) {
            const float* nrow = node_h + (size_t)(m0 + tr * 2 + i) * NH;
            float4 n0 = *(const float4*)&nrow[tc * 4];
            float4 n1 = *(const float4*)&nrow[64 + tc * 4];
            float* hrow = &H1sh[(tr * 2 + i) * 132];
            hrow[tc * 4 + 0] = acc[i][0] + n0.x; hrow[tc * 4 + 1] = acc[i][1] + n0.y;
            hrow[tc * 4 + 2] = acc[i][2] + n0.z; hrow[tc * 4 + 3] = acc[i][3] + n0.w;
            hrow[64 + tc * 4 + 0] = acc[i][4] + n1.x; hrow[64 + tc * 4 + 1] = acc[i][5] + n1.y;
            hrow[64 + tc * 4 + 2] = acc[i][6] + n1.z; hrow[64 + tc * 4 + 3] = acc[i][7] + n1.w;
        }
    }
    __syncthreads();

    for (int r = wid; r < 32; r += 8) {
        const int c0 = lane * 4;
        float v0 = H1sh[r * 132 + c0], v1 = H1sh[r * 132 + c0 + 1];
        float v2 = H1sh[r * 132 + c0 + 2], v3 = H1sh[r * 132 + c0 + 3];
        float s = v0 + v1 + v2 + v3;
#pragma unroll
        for (int o = 16; o; o >>= 1) s += __shfl_xor_sync(0xffffffffu, s, o);
        float mu = s * (1.f / 128.f);
        float d0 = v0 - mu, d1 = v1 - mu, d2 = v2 - mu, d3 = v3 - mu;
        float q = d0 * d0 + d1 * d1 + d2 * d2 + d3 * d3;
#pragma unroll
        for (int o = 16; o; o >>= 1) q += __shfl_xor_sync(0xffffffffu, q, o);
        float rs = rsqrtf(q * (1.f / 128.f) + 1e-5f);
        H1sh[r * 132 + c0]     = d0 * rs * g1[c0]     + b1[c0];
        H1sh[r * 132 + c0 + 1] = d1 * rs * g1[c0 + 1] + b1[c0 + 1];
        H1sh[r * 132 + c0 + 2] = d2 * rs * g1[c0 + 2] + b1[c0 + 2];
        H1sh[r * 132 + c0 + 3] = d3 * rs * g1[c0 + 3] + b1[c0 + 3];
    }

    for (int nc = 0; nc < 4; nc++) {
        __syncthreads();
        for (int i = tid; i < 4096; i += 256) {
            int k = i >> 5, c4 = i & 31;
            ((float4*)&Wsh[k * 128])[c4] = ((const float4*)&fW1[(size_t)k * 512 + nc * 128])[c4];
        }
        __syncthreads();
        float acc[2][8];
#pragma unroll
        for (int i = 0; i < 2; i++)
#pragma unroll
            for (int j = 0; j < 8; j++)
                acc[i][j] = fb1[nc * 128 + (j < 4 ? tc * 4 + j : 64 + tc * 4 + j - 4)];
#pragma unroll 4
        for (int kk = 0; kk < 128; kk++) {
            float4 b0 = *(const float4*)&Wsh[kk * 128 + tc * 4];
            float4 b1v = *(const float4*)&Wsh[kk * 128 + 64 + tc * 4];
#pragma unroll
            for (int i = 0; i < 2; i++) {
                float a = H1sh[(tr * 2 + i) * 132 + kk];
                acc[i][0] = fmaf(a, b0.x, acc[i][0]); acc[i][1] = fmaf(a, b0.y, acc[i][1]);
                acc[i][2] = fmaf(a, b0.z, acc[i][2]); acc[i][3] = fmaf(a, b0.w, acc[i][3]);
                acc[i][4] = fmaf(a, b1v.x, acc[i][4]); acc[i][5] = fmaf(a, b1v.y, acc[i][5]);
                acc[i][6] = fmaf(a, b1v.z, acc[i][6]); acc[i][7] = fmaf(a, b1v.w, acc[i][7]);
            }
        }
#pragma unroll
        for (int i = 0; i < 2; i++) {
            float* trow = &Tsh[(tr * 2 + i) * 516 + nc * 128];
#pragma unroll
            for (int j = 0; j < 4; j++) trow[tc * 4 + j]      = gelu_exact(acc[i][j]);
#pragma unroll
            for (int j = 0; j < 4; j++) trow[64 + tc * 4 + j] = gelu_exact(acc[i][4 + j]);
        }
    }

    float acc2[2][8];
#pragma unroll
    for (int i = 0; i < 2; i++)
#pragma unroll
        for (int j = 0; j < 8; j++)
            acc2[i][j] = fb2[(j < 4 ? tc * 4 + j : 64 + tc * 4 + j - 4)];
    for (int kc = 0; kc < 4; kc++) {
        __syncthreads();
        for (int i = tid; i < 4096; i += 256) {
            int k = i >> 5, c4 = i & 31;
            ((float4*)&Wsh[k * 128])[c4] = ((const float4*)&fW2[(size_t)(kc * 128 + k) * 128])[c4];
        }
        __syncthreads();
#pragma unroll 4
        for (int kk = 0; kk < 128; kk++) {
            float4 b0 = *(const float4*)&Wsh[kk * 128 + tc * 4];
            float4 b1v = *(const float4*)&Wsh[kk * 128 + 64 + tc * 4];
#pragma unroll
            for (int i = 0; i < 2; i++) {
                float a = Tsh[(tr * 2 + i) * 516 + kc * 128 + kk];
                acc2[i][0] = fmaf(a, b0.x, acc2[i][0]); acc2[i][1] = fmaf(a, b0.y, acc2[i][1]);
                acc2[i][2] = fmaf(a, b0.z, acc2[i][2]); acc2[i][3] = fmaf(a, b0.w, acc2[i][3]);
                acc2[i][4] = fmaf(a, b1v.x, acc2[i][4]); acc2[i][5] = fmaf(a, b1v.y, acc2[i][5]);
                acc2[i][6] = fmaf(a, b1v.z, acc2[i][6]); acc2[i][7] = fmaf(a, b1v.w, acc2[i][7]);
            }
        }
    }

    __syncthreads();
    float* Vsh = Tsh;
#pragma unroll
    for (int i = 0; i < 2; i++) {
        const int r = tr * 2 + i;
#pragma unroll
        for (int j = 0; j < 4; j++) Vsh[r * 132 + tc * 4 + j]      = H1sh[r * 132 + tc * 4 + j] + acc2[i][j];
#pragma unroll
        for (int j = 0; j < 4; j++) Vsh[r * 132 + 64 + tc * 4 + j] = H1sh[r * 132 + 64 + tc * 4 + j] + acc2[i][4 + j];
    }
    __syncthreads();
    for (int r = wid; r < 32; r += 8) {
        const int c0 = lane * 4;
        float v0 = Vsh[r * 132 + c0], v1 = Vsh[r * 132 + c0 + 1];
        float v2 = Vsh[r * 132 + c0 + 2], v3 = Vsh[r * 132 + c0 + 3];
        float s = v0 + v1 + v2 + v3;
#pragma unroll
        for (int o = 16; o; o >>= 1) s += __shfl_xor_sync(0xffffffffu, s, o);
        float mu = s * (1.f / 128.f);
        float d0 = v0 - mu, d1 = v1 - mu, d2 = v2 - mu, d3 = v3 - mu;
        float q = d0 * d0 + d1 * d1 + d2 * d2 + d3 * d3;
#pragma unroll
        for (int o = 16; o; o >>= 1) q += __shfl_xor_sync(0xffffffffu, q, o);
        float rs = rsqrtf(q * (1.f / 128.f) + 1e-5f);
        float4 o4;
        o4.x = d0 * rs * g2[c0]     + b2[c0];
        o4.y = d1 * rs * g2[c0 + 1] + b2[c0 + 1];
        o4.z = d2 * rs * g2[c0 + 2] + b2[c0 + 2];
        o4.w = d3 * rs * g2[c0 + 3] + b2[c0 + 3];
        *(float4*)&out[(size_t)(m0 + r) * NH + c0] = o4;
    }
}

// ---------------------------------------------------------------------------
extern "C" void kernel_launch(void* const* d_in, const int* in_sizes, int n_in,
                              void* d_out, int out_size) {
    const float* node_h   = (const float*)d_in[0];
    const float* edge_h   = (const float*)d_in[1];
    const int*   edge_idx = (const int*)d_in[2];
    const float* seq_emb  = (const float*)d_in[3];
    const float* ar_mask  = (const float*)d_in[4];
    const float* mW1 = (const float*)d_in[5];
    const float* mb1 = (const float*)d_in[6];
    const float* mW2 = (const float*)d_in[7];
    const float* mb2 = (const float*)d_in[8];
    const float* mW3 = (const float*)d_in[9];
    const float* mb3 = (const float*)d_in[10];
    const float* fW1 = (const float*)d_in[11];
    const float* fb1 = (const float*)d_in[12];
    const float* fW2 = (const float*)d_in[13];
    const float* fb2 = (const float*)d_in[14];
    const float* g1  = (const float*)d_in[15];
    const float* b1  = (const float*)d_in[16];
    const float* g2  = (const float*)d_in[17];
    const float* b2  = (const float*)d_in[18];
    float* out = (float*)d_out;

    int dev = 0;
    cudaGetDevice(&dev);
    int nsm = 148;
    cudaDeviceGetAttribute(&nsm, cudaDevAttrMultiProcessorCount, dev);

    const size_t smem1 = (size_t)(16384 + 64 * 132) * sizeof(float);
    const size_t smem3 = (size_t)(32 * 132 + 32 * 516 + 16384) * sizeof(float);

    cudaFuncSetAttribute(k1_pre, cudaFuncAttributeMaxDynamicSharedMemorySize, (int)smem1);
    cudaFuncSetAttribute(k2_msg, cudaFuncAttributeMaxDynamicSharedMemorySize, (int)S_K2TOT);
    cudaFuncSetAttribute(k3_ff,  cudaFuncAttributeMaxDynamicSharedMemorySize, (int)smem3);

    dim3 grid1(NRES / 64, 3);
    k1_pre<<<grid1, 256, smem1>>>(node_h, seq_emb, mW1);

    const int ngroups = NRES / 8;   // 1024 groups of 384 edges
    k2_msg<<<nsm, 512, S_K2TOT>>>(edge_h, edge_idx, ar_mask,
                                  mW1, mb1, mW2, mb2, ngroups);

    k3_ff<<<NRES / 32, 256, smem3>>>(node_h, mW3, mb3, fW1, fb1, fW2, fb2,
                                     g1, b1, g2, b2, out);
}

// round 7
// speedup vs baseline: 2.2612x; 1.5679x over previous
#include <cuda_runtime.h>
#include <cuda_fp16.h>
#include <math.h>
#include <stdint.h>

#define NRES 8192
#define NK   48
#define NH   128

__device__ float g_Pi[NRES * NH];
__device__ float g_Pj[NRES * NH];
__device__ float g_Ps[NRES * NH];
__device__ float g_S [NRES * NH];

__device__ __forceinline__ float gelu_exact(float x) {
    return 0.5f * x * (1.0f + erff(x * 0.7071067811865475f));
}
__device__ __forceinline__ uint32_t smem_u32(const void* p) {
    uint32_t a;
    asm("{ .reg .u64 t; cvta.to.shared.u64 t, %1; cvt.u32.u64 %0, t; }" : "=r"(a) : "l"(p));
    return a;
}
__device__ __forceinline__ uint32_t pack_h2(float a, float b) {
    __half2 h = __floats2half2_rn(a, b);
    return *reinterpret_cast<uint32_t*>(&h);
}
__device__ __forceinline__ void ldm_x4(uint32_t& r0, uint32_t& r1, uint32_t& r2, uint32_t& r3, uint32_t a) {
    asm volatile("ldmatrix.sync.aligned.m8n8.x4.shared.b16 {%0,%1,%2,%3}, [%4];"
                 : "=r"(r0), "=r"(r1), "=r"(r2), "=r"(r3) : "r"(a));
}
__device__ __forceinline__ void ldm_x2(uint32_t& r0, uint32_t& r1, uint32_t a) {
    asm volatile("ldmatrix.sync.aligned.m8n8.x2.shared.b16 {%0,%1}, [%2];"
                 : "=r"(r0), "=r"(r1) : "r"(a));
}
__device__ __forceinline__ void mma_f16(float* c, uint32_t a0, uint32_t a1, uint32_t a2, uint32_t a3,
                                        uint32_t b0, uint32_t b1) {
    asm volatile("mma.sync.aligned.m16n8k16.row.col.f32.f16.f16.f32 "
                 "{%0,%1,%2,%3}, {%4,%5,%6,%7}, {%8,%9}, {%0,%1,%2,%3};"
                 : "+f"(c[0]), "+f"(c[1]), "+f"(c[2]), "+f"(c[3])
                 : "r"(a0), "r"(a1), "r"(a2), "r"(a3), "r"(b0), "r"(b1));
}

// ---------------------------------------------------------------------------
// Kernel 1: Pi/Pj/Ps projections (fp32, conflict-free columns) — proven
// ---------------------------------------------------------------------------
__global__ __launch_bounds__(256) void k1_pre(const float* __restrict__ node_h,
                                              const float* __restrict__ seq_emb,
                                              const float* __restrict__ mW1) {
    extern __shared__ float sm1[];
    float* Wsh = sm1;
    float* Ash = sm1 + 16384;
    const int tid   = threadIdx.x;
    const int which = blockIdx.y;
    const float* A    = (which == 2) ? seq_emb : node_h;
    const float* Wsrc = mW1 + (size_t)(which == 0 ? 0 : (which == 1 ? 128 : 384)) * NH;
    float* out = (which == 0) ? g_Pi : (which == 1 ? g_Pj : g_Ps);

    for (int i = tid; i < 4096; i += 256) ((float4*)Wsh)[i] = ((const float4*)Wsrc)[i];
    const int m0 = blockIdx.x * 64;
    for (int i = tid; i < 2048; i += 256) {
        int r = i >> 5, c4 = i & 31;
        *(float4*)&Ash[r * 132 + c4 * 4] = ((const float4*)(A + (size_t)(m0 + r) * NH))[c4];
    }
    __syncthreads();
    const int tc = tid & 15, tr = tid >> 4;
    float acc[4][8];
#pragma unroll
    for (int i = 0; i < 4; i++)
#pragma unroll
        for (int j = 0; j < 8; j++) acc[i][j] = 0.f;
#pragma unroll 4
    for (int kk = 0; kk < 128; kk++) {
        float4 b0 = *(const float4*)&Wsh[kk * 128 + tc * 4];
        float4 b1 = *(const float4*)&Wsh[kk * 128 + 64 + tc * 4];
#pragma unroll
        for (int i = 0; i < 4; i++) {
            float a = Ash[(tr * 4 + i) * 132 + kk];
            acc[i][0] = fmaf(a, b0.x, acc[i][0]); acc[i][1] = fmaf(a, b0.y, acc[i][1]);
            acc[i][2] = fmaf(a, b0.z, acc[i][2]); acc[i][3] = fmaf(a, b0.w, acc[i][3]);
            acc[i][4] = fmaf(a, b1.x, acc[i][4]); acc[i][5] = fmaf(a, b1.y, acc[i][5]);
            acc[i][6] = fmaf(a, b1.z, acc[i][6]); acc[i][7] = fmaf(a, b1.w, acc[i][7]);
        }
    }
#pragma unroll
    for (int i = 0; i < 4; i++) {
        size_t r = (size_t)(m0 + tr * 4 + i) * NH;
        *(float4*)&out[r + tc * 4]      = make_float4(acc[i][0], acc[i][1], acc[i][2], acc[i][3]);
        *(float4*)&out[r + 64 + tc * 4] = make_float4(acc[i][4], acc[i][5], acc[i][6], acc[i][7]);
    }
}

// ---------------------------------------------------------------------------
// Kernel 2: per-edge MLP (fp16 A, fp16 hi/lo W, 2 mma passes/GEMM).
// cp.async pipeline. Epilogue-2: warp shuffle segmented reduction (16x fewer
// smem atomics than per-element atomicAdd).
// ---------------------------------------------------------------------------
#define LDB 272u
#define S_W1H 0u
#define S_W1L 34816u
#define S_W2H 69632u
#define S_W2L 104448u
#define S_A   139264u
#define S_STG 174080u
#define S_SSUM 223232u
#define S_IDX 227328u
#define S_AM  228352u
#define S_MB  229376u
#define S_K2TOT 230400u

__device__ __forceinline__ void do_prefetch(uint32_t sb, const float* edge_h,
                                            const int* edge_idx, const float* ar_mask,
                                            int row0, int pp, int tid) {
    const char* src = (const char*)(edge_h + (size_t)row0 * NH);
#pragma unroll
    for (int k = 0; k < 6; k++) {
        uint32_t off = (uint32_t)(tid + k * 512) * 16u;
        asm volatile("cp.async.cg.shared.global [%0], [%1], 16;"
                     :: "r"(sb + S_STG + off), "l"(src + off));
    }
    if (tid < 128)
        asm volatile("cp.async.ca.shared.global [%0], [%1], 4;"
                     :: "r"(sb + S_IDX + (uint32_t)pp * 512u + (uint32_t)tid * 4u),
                        "l"(edge_idx + row0 + tid));
    else if (tid < 256)
        asm volatile("cp.async.ca.shared.global [%0], [%1], 4;"
                     :: "r"(sb + S_AM + (uint32_t)pp * 512u + (uint32_t)(tid - 128) * 4u),
                        "l"(ar_mask + row0 + (tid - 128)));
    asm volatile("cp.async.commit_group;" ::: "memory");
}

__global__ __launch_bounds__(512) void k2_msg(const float* __restrict__ edge_h,
                                              const int*   __restrict__ edge_idx,
                                              const float* __restrict__ ar_mask,
                                              const float* __restrict__ mW1,
                                              const float* __restrict__ mb1,
                                              const float* __restrict__ mW2,
                                              const float* __restrict__ mb2,
                                              int ngroups) {
    extern __shared__ char sm[];
    const int tid  = threadIdx.x;
    const int w    = tid >> 5, lane = tid & 31;
    const int gid  = lane >> 2, t4 = lane & 3;
    const int wm   = w >> 2, wn = w & 3;
    const int m_base = wm * 32, n_base = wn * 32;
    const uint32_t sb = smem_u32(sm);

    float* SSUM = (float*)(sm + S_SSUM);
    float* MB   = (float*)(sm + S_MB);
    float* STG  = (float*)(sm + S_STG);

    if (tid < 128) MB[tid] = mb1[tid];
    else if (tid < 256) MB[tid] = mb2[tid - 128];

    for (int idx = tid; idx < 16384; idx += 512) {
        const int n = idx >> 7, k = idx & 127;
        float w1 = mW1[(size_t)(256 + k) * NH + n];
        float w2 = mW2[(size_t)k * NH + n];
        __half h1 = __float2half_rn(w1), l1 = __float2half_rn(w1 - __half2float(h1));
        __half h2 = __float2half_rn(w2), l2 = __float2half_rn(w2 - __half2float(h2));
        const uint32_t o = (uint32_t)n * LDB + (uint32_t)k * 2u;
        *(__half*)(sm + S_W1H + o) = h1;
        *(__half*)(sm + S_W1L + o) = l1;
        *(__half*)(sm + S_W2H + o) = h2;
        *(__half*)(sm + S_W2L + o) = l2;
    }

    const uint32_t aBase = sb + S_A + (uint32_t)(m_base + (lane & 15)) * LDB
                         + (uint32_t)((lane >> 4) * 16);
    const uint32_t b_off = (uint32_t)(lane & 7) * LDB + (uint32_t)(((lane >> 3) & 1) * 16);
    uint32_t bOf[4];
#pragma unroll
    for (int j = 0; j < 4; j++)
        bOf[j] = (uint32_t)(n_base + j * 8) * LDB + b_off;

    int pp = 0;
    if ((int)blockIdx.x < ngroups)
        do_prefetch(sb, edge_h, edge_idx, ar_mask, blockIdx.x * 384, 0, tid);

    for (int g = blockIdx.x; g < ngroups; g += gridDim.x) {
        for (int t = 0; t < 3; t++) {
            const int row0 = g * 384 + t * 128;
            asm volatile("cp.async.wait_group 0;" ::: "memory");
            __syncthreads();
            if (t == 0)
                for (int i = tid; i < 1024; i += 512) SSUM[i] = 0.f;

            // staged rows 0-95 -> A fp16
#pragma unroll
            for (int k2i = 0; k2i < 6; k2i++) {
                const int i = tid + k2i * 512;
                const int r = i >> 5, c4 = i & 31;
                float4 e = *(const float4*)((const char*)STG + (size_t)i * 16);
                const uint32_t o = (uint32_t)r * LDB + (uint32_t)c4 * 8u;
                *(uint2*)(sm + S_A + o) = make_uint2(pack_h2(e.x, e.y), pack_h2(e.z, e.w));
            }
            // direct rows 96-127
#pragma unroll
            for (int k2i = 0; k2i < 2; k2i++) {
                const int i = tid + k2i * 512;
                const int r = 96 + (i >> 5), c4 = i & 31;
                float4 e = ((const float4*)(edge_h + (size_t)(row0 + r) * NH))[c4];
                const uint32_t o = (uint32_t)r * LDB + (uint32_t)c4 * 8u;
                *(uint2*)(sm + S_A + o) = make_uint2(pack_h2(e.x, e.y), pack_h2(e.z, e.w));
            }
            __syncthreads();

            // prefetch next tile
            {
                int nt = t + 1, ng = g;
                if (nt == 3) { nt = 0; ng = g + gridDim.x; }
                if (ng < ngroups)
                    do_prefetch(sb, edge_h, edge_idx, ar_mask, ng * 384 + nt * 128, pp ^ 1, tid);
            }

            const int*   IDXc = (const int*)(sm + S_IDX) + pp * 128;
            const float* AMc  = (const float*)(sm + S_AM) + pp * 128;

            float acc[2][4][4];

            // GEMM1 acc init: Pi + Pj + am*Ps + mb1
#pragma unroll
            for (int i = 0; i < 2; i++) {
                const int rA = m_base + i * 16 + gid;
                const int resA = (row0 + rA) / NK,  resB = (row0 + rA + 8) / NK;
                const int nbrA = IDXc[rA],          nbrB = IDXc[rA + 8];
                const float amA = AMc[rA],          amB = AMc[rA + 8];
                const float* PiA = g_Pi + (size_t)resA * NH;
                const float* PiB = g_Pi + (size_t)resB * NH;
                const float* PjA = g_Pj + (size_t)nbrA * NH;
                const float* PjB = g_Pj + (size_t)nbrB * NH;
                const float* PsA = g_Ps + (size_t)nbrA * NH;
                const float* PsB = g_Ps + (size_t)nbrB * NH;
#pragma unroll
                for (int j = 0; j < 4; j++) {
                    const int n_e = n_base + j * 8 + t4 * 2;
                    float2 piA = *(const float2*)&PiA[n_e], piB = *(const float2*)&PiB[n_e];
                    float2 pjA = *(const float2*)&PjA[n_e], pjB = *(const float2*)&PjB[n_e];
                    float2 psA = *(const float2*)&PsA[n_e], psB = *(const float2*)&PsB[n_e];
                    float2 mb = *(const float2*)&MB[n_e];
                    acc[i][j][0] = piA.x + pjA.x + amA * psA.x + mb.x;
                    acc[i][j][1] = piA.y + pjA.y + amA * psA.y + mb.y;
                    acc[i][j][2] = piB.x + pjB.x + amB * psB.x + mb.x;
                    acc[i][j][3] = piB.y + pjB.y + amB * psB.y + mb.y;
                }
            }
            // GEMM1: acc += E @ (W1h + W1l)
#pragma unroll
            for (int ks = 0; ks < 8; ks++) {
                const uint32_t ko = (uint32_t)ks * 32u;
                uint32_t a[2][4], bh[4][2], bl[4][2];
                ldm_x4(a[0][0], a[0][1], a[0][2], a[0][3], aBase + ko);
                ldm_x4(a[1][0], a[1][1], a[1][2], a[1][3], aBase + 16u * LDB + ko);
#pragma unroll
                for (int j = 0; j < 4; j++) {
                    ldm_x2(bh[j][0], bh[j][1], sb + S_W1H + bOf[j] + ko);
                    ldm_x2(bl[j][0], bl[j][1], sb + S_W1L + bOf[j] + ko);
                }
#pragma unroll
                for (int i = 0; i < 2; i++)
#pragma unroll
                    for (int j = 0; j < 4; j++) {
                        mma_f16(acc[i][j], a[i][0], a[i][1], a[i][2], a[i][3], bh[j][0], bh[j][1]);
                        mma_f16(acc[i][j], a[i][0], a[i][1], a[i][2], a[i][3], bl[j][0], bl[j][1]);
                    }
            }
            __syncthreads();

            // epilogue 1: X1 = gelu(acc) -> A
#pragma unroll
            for (int i = 0; i < 2; i++) {
                const int m_e = m_base + i * 16 + gid;
#pragma unroll
                for (int j = 0; j < 4; j++) {
                    const int n_e = n_base + j * 8 + t4 * 2;
                    float v0 = gelu_exact(acc[i][j][0]), v1 = gelu_exact(acc[i][j][1]);
                    float v2 = gelu_exact(acc[i][j][2]), v3 = gelu_exact(acc[i][j][3]);
                    const uint32_t o0 = (uint32_t)m_e * LDB + (uint32_t)n_e * 2u;
                    const uint32_t o1 = o0 + 8u * LDB;
                    *(uint32_t*)(sm + S_A + o0) = pack_h2(v0, v1);
                    *(uint32_t*)(sm + S_A + o1) = pack_h2(v2, v3);
                }
            }
            __syncthreads();

            // GEMM2: acc = mb2 + X1 @ (W2h + W2l)
#pragma unroll
            for (int i = 0; i < 2; i++)
#pragma unroll
                for (int j = 0; j < 4; j++) {
                    float2 mb = *(const float2*)&MB[128 + n_base + j * 8 + t4 * 2];
                    acc[i][j][0] = mb.x; acc[i][j][1] = mb.y;
                    acc[i][j][2] = mb.x; acc[i][j][3] = mb.y;
                }
#pragma unroll
            for (int ks = 0; ks < 8; ks++) {
                const uint32_t ko = (uint32_t)ks * 32u;
                uint32_t a[2][4], bh[4][2], bl[4][2];
                ldm_x4(a[0][0], a[0][1], a[0][2], a[0][3], aBase + ko);
                ldm_x4(a[1][0], a[1][1], a[1][2], a[1][3], aBase + 16u * LDB + ko);
#pragma unroll
                for (int j = 0; j < 4; j++) {
                    ldm_x2(bh[j][0], bh[j][1], sb + S_W2H + bOf[j] + ko);
                    ldm_x2(bl[j][0], bl[j][1], sb + S_W2L + bOf[j] + ko);
                }
#pragma unroll
                for (int i = 0; i < 2; i++)
#pragma unroll
                    for (int j = 0; j < 4; j++) {
                        mma_f16(acc[i][j], a[i][0], a[i][1], a[i][2], a[i][3], bh[j][0], bh[j][1]);
                        mma_f16(acc[i][j], a[i][0], a[i][1], a[i][2], a[i][3], bl[j][0], bl[j][1]);
                    }
            }

            // ---- epilogue 2: gelu -> warp-shuffle segmented reduce -> few atomics ----
            {
                const int R0  = t * 128 + m_base;          // group-local first row of warp slice
                const int rl0 = R0 / NK;                   // residue segment of first row
                const int bb  = (rl0 + 1) * NK - R0;       // boundary offset in [1..48]
#pragma unroll
                for (int j = 0; j < 4; j++) {
#pragma unroll
                    for (int p = 0; p < 2; p++) {
                        float y0 = gelu_exact(acc[0][j][p]);       // row off gid
                        float y1 = gelu_exact(acc[0][j][p + 2]);   // row off gid+8
                        float y2 = gelu_exact(acc[1][j][p]);       // row off gid+16
                        float y3 = gelu_exact(acc[1][j][p + 2]);   // row off gid+24
                        float s0 = 0.f, s1 = 0.f;
                        if (gid      < bb) s0 += y0; else s1 += y0;
                        if (gid + 8  < bb) s0 += y1; else s1 += y1;
                        if (gid + 16 < bb) s0 += y2; else s1 += y2;
                        if (gid + 24 < bb) s0 += y3; else s1 += y3;
#pragma unroll
                        for (int o = 4; o <= 16; o <<= 1) {
                            s0 += __shfl_xor_sync(0xffffffffu, s0, o);
                            s1 += __shfl_xor_sync(0xffffffffu, s1, o);
                        }
                        if (gid == 0) {
                            const int c = n_base + j * 8 + t4 * 2 + p;
                            atomicAdd(&SSUM[rl0 * 128 + c], s0);
                            if (bb < 32) atomicAdd(&SSUM[(rl0 + 1) * 128 + c], s1);
                        }
                    }
                }
            }
            pp ^= 1;
        }
        __syncthreads();
        for (int i = tid; i < 1024; i += 512)
            g_S[(size_t)g * 1024 + i] = SSUM[i];
    }
}

// ---------------------------------------------------------------------------
// Kernel 3: agg = S@W3 + 48*mb3; LN1; FFN; LN2 (proven)
// ---------------------------------------------------------------------------
__global__ __launch_bounds__(256) void k3_ff(const float* __restrict__ node_h,
                                             const float* __restrict__ mW3,
                                             const float* __restrict__ mb3,
                                             const float* __restrict__ fW1,
                                             const float* __restrict__ fb1,
                                             const float* __restrict__ fW2,
                                             const float* __restrict__ fb2,
                                             const float* __restrict__ g1,
                                             const float* __restrict__ b1,
                                             const float* __restrict__ g2,
                                             const float* __restrict__ b2,
                                             float* __restrict__ out) {
    extern __shared__ float sm3[];
    float* H1sh = sm3;
    float* Tsh  = sm3 + 32 * 132;
    float* Wsh  = sm3 + 32 * 132 + 32 * 516;

    const int tid = threadIdx.x;
    const int wid = tid >> 5, lane = tid & 31;
    const int m0  = blockIdx.x * 32;
    const int tc = tid & 15, tr = tid >> 4;

    for (int i = tid; i < 4096; i += 256) ((float4*)Wsh)[i] = ((const float4*)mW3)[i];
    for (int i = tid; i < 1024; i += 256) {
        int r = i >> 5, c4 = i & 31;
        *(float4*)&Tsh[r * 132 + c4 * 4] = ((const float4*)(g_S + (size_t)(m0 + r) * NH))[c4];
    }
    __syncthreads();

    {
        float acc[2][8];
#pragma unroll
        for (int i = 0; i < 2; i++)
#pragma unroll
            for (int j = 0; j < 8; j++)
                acc[i][j] = 48.f * mb3[(j < 4 ? tc * 4 + j : 64 + tc * 4 + j - 4)];
#pragma unroll 4
        for (int kk = 0; kk < 128; kk++) {
            float4 b0 = *(const float4*)&Wsh[kk * 128 + tc * 4];
            float4 b1v = *(const float4*)&Wsh[kk * 128 + 64 + tc * 4];
#pragma unroll
            for (int i = 0; i < 2; i++) {
                float a = Tsh[(tr * 2 + i) * 132 + kk];
                acc[i][0] = fmaf(a, b0.x, acc[i][0]); acc[i][1] = fmaf(a, b0.y, acc[i][1]);
                acc[i][2] = fmaf(a, b0.z, acc[i][2]); acc[i][3] = fmaf(a, b0.w, acc[i][3]);
                acc[i][4] = fmaf(a, b1v.x, acc[i][4]); acc[i][5] = fmaf(a, b1v.y, acc[i][5]);
                acc[i][6] = fmaf(a, b1v.z, acc[i][6]); acc[i][7] = fmaf(a, b1v.w, acc[i][7]);
            }
        }
#pragma unroll
        for (int i = 0; i < 2; i++) {
            const float* nrow = node_h + (size_t)(m0 + tr * 2 + i) * NH;
            float4 n0 = *(const float4*)&nrow[tc * 4];
            float4 n1 = *(const float4*)&nrow[64 + tc * 4];
            float* hrow = &H1sh[(tr * 2 + i) * 132];
            hrow[tc * 4 + 0] = acc[i][0] + n0.x; hrow[tc * 4 + 1] = acc[i][1] + n0.y;
            hrow[tc * 4 + 2] = acc[i][2] + n0.z; hrow[tc * 4 + 3] = acc[i][3] + n0.w;
            hrow[64 + tc * 4 + 0] = acc[i][4] + n1.x; hrow[64 + tc * 4 + 1] = acc[i][5] + n1.y;
            hrow[64 + tc * 4 + 2] = acc[i][6] + n1.z; hrow[64 + tc * 4 + 3] = acc[i][7] + n1.w;
        }
    }
    __syncthreads();

    for (int r = wid; r < 32; r += 8) {
        const int c0 = lane * 4;
        float v0 = H1sh[r * 132 + c0], v1 = H1sh[r * 132 + c0 + 1];
        float v2 = H1sh[r * 132 + c0 + 2], v3 = H1sh[r * 132 + c0 + 3];
        float s = v0 + v1 + v2 + v3;
#pragma unroll
        for (int o = 16; o; o >>= 1) s += __shfl_xor_sync(0xffffffffu, s, o);
        float mu = s * (1.f / 128.f);
        float d0 = v0 - mu, d1 = v1 - mu, d2 = v2 - mu, d3 = v3 - mu;
        float q = d0 * d0 + d1 * d1 + d2 * d2 + d3 * d3;
#pragma unroll
        for (int o = 16; o; o >>= 1) q += __shfl_xor_sync(0xffffffffu, q, o);
        float rs = rsqrtf(q * (1.f / 128.f) + 1e-5f);
        H1sh[r * 132 + c0]     = d0 * rs * g1[c0]     + b1[c0];
        H1sh[r * 132 + c0 + 1] = d1 * rs * g1[c0 + 1] + b1[c0 + 1];
        H1sh[r * 132 + c0 + 2] = d2 * rs * g1[c0 + 2] + b1[c0 + 2];
        H1sh[r * 132 + c0 + 3] = d3 * rs * g1[c0 + 3] + b1[c0 + 3];
    }

    for (int nc = 0; nc < 4; nc++) {
        __syncthreads();
        for (int i = tid; i < 4096; i += 256) {
            int k = i >> 5, c4 = i & 31;
            ((float4*)&Wsh[k * 128])[c4] = ((const float4*)&fW1[(size_t)k * 512 + nc * 128])[c4];
        }
        __syncthreads();
        float acc[2][8];
#pragma unroll
        for (int i = 0; i < 2; i++)
#pragma unroll
            for (int j = 0; j < 8; j++)
                acc[i][j] = fb1[nc * 128 + (j < 4 ? tc * 4 + j : 64 + tc * 4 + j - 4)];
#pragma unroll 4
        for (int kk = 0; kk < 128; kk++) {
            float4 b0 = *(const float4*)&Wsh[kk * 128 + tc * 4];
            float4 b1v = *(const float4*)&Wsh[kk * 128 + 64 + tc * 4];
#pragma unroll
            for (int i = 0; i < 2; i++) {
                float a = H1sh[(tr * 2 + i) * 132 + kk];
                acc[i][0] = fmaf(a, b0.x, acc[i][0]); acc[i][1] = fmaf(a, b0.y, acc[i][1]);
                acc[i][2] = fmaf(a, b0.z, acc[i][2]); acc[i][3] = fmaf(a, b0.w, acc[i][3]);
                acc[i][4] = fmaf(a, b1v.x, acc[i][4]); acc[i][5] = fmaf(a, b1v.y, acc[i][5]);
                acc[i][6] = fmaf(a, b1v.z, acc[i][6]); acc[i][7] = fmaf(a, b1v.w, acc[i][7]);
            }
        }
#pragma unroll
        for (int i = 0; i < 2; i++) {
            float* trow = &Tsh[(tr * 2 + i) * 516 + nc * 128];
#pragma unroll
            for (int j = 0; j < 4; j++) trow[tc * 4 + j]      = gelu_exact(acc[i][j]);
#pragma unroll
            for (int j = 0; j < 4; j++) trow[64 + tc * 4 + j] = gelu_exact(acc[i][4 + j]);
        }
    }

    float acc2[2][8];
#pragma unroll
    for (int i = 0; i < 2; i++)
#pragma unroll
        for (int j = 0; j < 8; j++)
            acc2[i][j] = fb2[(j < 4 ? tc * 4 + j : 64 + tc * 4 + j - 4)];
    for (int kc = 0; kc < 4; kc++) {
        __syncthreads();
        for (int i = tid; i < 4096; i += 256) {
            int k = i >> 5, c4 = i & 31;
            ((float4*)&Wsh[k * 128])[c4] = ((const float4*)&fW2[(size_t)(kc * 128 + k) * 128])[c4];
        }
        __syncthreads();
#pragma unroll 4
        for (int kk = 0; kk < 128; kk++) {
            float4 b0 = *(const float4*)&Wsh[kk * 128 + tc * 4];
            float4 b1v = *(const float4*)&Wsh[kk * 128 + 64 + tc * 4];
#pragma unroll
            for (int i = 0; i < 2; i++) {
                float a = Tsh[(tr * 2 + i) * 516 + kc * 128 + kk];
                acc2[i][0] = fmaf(a, b0.x, acc2[i][0]); acc2[i][1] = fmaf(a, b0.y, acc2[i][1]);
                acc2[i][2] = fmaf(a, b0.z, acc2[i][2]); acc2[i][3] = fmaf(a, b0.w, acc2[i][3]);
                acc2[i][4] = fmaf(a, b1v.x, acc2[i][4]); acc2[i][5] = fmaf(a, b1v.y, acc2[i][5]);
                acc2[i][6] = fmaf(a, b1v.z, acc2[i][6]); acc2[i][7] = fmaf(a, b1v.w, acc2[i][7]);
            }
        }
    }

    __syncthreads();
    float* Vsh = Tsh;
#pragma unroll
    for (int i = 0; i < 2; i++) {
        const int r = tr * 2 + i;
#pragma unroll
        for (int j = 0; j < 4; j++) Vsh[r * 132 + tc * 4 + j]      = H1sh[r * 132 + tc * 4 + j] + acc2[i][j];
#pragma unroll
        for (int j = 0; j < 4; j++) Vsh[r * 132 + 64 + tc * 4 + j] = H1sh[r * 132 + 64 + tc * 4 + j] + acc2[i][4 + j];
    }
    __syncthreads();
    for (int r = wid; r < 32; r += 8) {
        const int c0 = lane * 4;
        float v0 = Vsh[r * 132 + c0], v1 = Vsh[r * 132 + c0 + 1];
        float v2 = Vsh[r * 132 + c0 + 2], v3 = Vsh[r * 132 + c0 + 3];
        float s = v0 + v1 + v2 + v3;
#pragma unroll
        for (int o = 16; o; o >>= 1) s += __shfl_xor_sync(0xffffffffu, s, o);
        float mu = s * (1.f / 128.f);
        float d0 = v0 - mu, d1 = v1 - mu, d2 = v2 - mu, d3 = v3 - mu;
        float q = d0 * d0 + d1 * d1 + d2 * d2 + d3 * d3;
#pragma unroll
        for (int o = 16; o; o >>= 1) q += __shfl_xor_sync(0xffffffffu, q, o);
        float rs = rsqrtf(q * (1.f / 128.f) + 1e-5f);
        float4 o4;
        o4.x = d0 * rs * g2[c0]     + b2[c0];
        o4.y = d1 * rs * g2[c0 + 1] + b2[c0 + 1];
        o4.z = d2 * rs * g2[c0 + 2] + b2[c0 + 2];
        o4.w = d3 * rs * g2[c0 + 3] + b2[c0 + 3];
        *(float4*)&out[(size_t)(m0 + r) * NH + c0] = o4;
    }
}

// ---------------------------------------------------------------------------
extern "C" void kernel_launch(void* const* d_in, const int* in_sizes, int n_in,
                              void* d_out, int out_size) {
    const float* node_h   = (const float*)d_in[0];
    const float* edge_h   = (const float*)d_in[1];
    const int*   edge_idx = (const int*)d_in[2];
    const float* seq_emb  = (const float*)d_in[3];
    const float* ar_mask  = (const float*)d_in[4];
    const float* mW1 = (const float*)d_in[5];
    const float* mb1 = (const float*)d_in[6];
    const float* mW2 = (const float*)d_in[7];
    const float* mb2 = (const float*)d_in[8];
    const float* mW3 = (const float*)d_in[9];
    const float* mb3 = (const float*)d_in[10];
    const float* fW1 = (const float*)d_in[11];
    const float* fb1 = (const float*)d_in[12];
    const float* fW2 = (const float*)d_in[13];
    const float* fb2 = (const float*)d_in[14];
    const float* g1  = (const float*)d_in[15];
    const float* b1  = (const float*)d_in[16];
    const float* g2  = (const float*)d_in[17];
    const float* b2  = (const float*)d_in[18];
    float* out = (float*)d_out;

    int dev = 0;
    cudaGetDevice(&dev);
    int nsm = 148;
    cudaDeviceGetAttribute(&nsm, cudaDevAttrMultiProcessorCount, dev);

    const size_t smem1 = (size_t)(16384 + 64 * 132) * sizeof(float);
    const size_t smem3 = (size_t)(32 * 132 + 32 * 516 + 16384) * sizeof(float);

    cudaFuncSetAttribute(k1_pre, cudaFuncAttributeMaxDynamicSharedMemorySize, (int)smem1);
    cudaFuncSetAttribute(k2_msg, cudaFuncAttributeMaxDynamicSharedMemorySize, (int)S_K2TOT);
    cudaFuncSetAttribute(k3_ff,  cudaFuncAttributeMaxDynamicSharedMemorySize, (int)smem3);

    dim3 grid1(NRES / 64, 3);
    k1_pre<<<grid1, 256, smem1>>>(node_h, seq_emb, mW1);

    const int ngroups = NRES / 8;
    k2_msg<<<nsm, 512, S_K2TOT>>>(edge_h, edge_idx, ar_mask,
                                  mW1, mb1, mW2, mb2, ngroups);

    k3_ff<<<NRES / 32, 256, smem3>>>(node_h, mW3, mb3, fW1, fb1, fW2, fb2,
                                     g1, b1, g2, b2, out);
}